// round 11
// baseline (speedup 1.0000x reference)
#include <cuda_runtime.h>
#include <cuda_bf16.h>
#include <cstdint>

// ---------------- scratch (no cudaMalloc allowed) ----------------
__device__ __nv_bfloat16 g_A2[4096 * 2304];          // x-split, later ao-split [hi|lo|hi]
__device__ __nv_bfloat16 g_B1[2304 * 2304];          // qkv_w split [hi|hi|lo]
__device__ __nv_bfloat16 g_B2[768 * 2304];           // proj_w split [hi|hi|lo]
__device__ __nv_bfloat16 g_Q2[24 * 2048 * 128];      // per-head hi|lo (Q pre-scaled)
__device__ __nv_bfloat16 g_K2[24 * 2048 * 128];
__device__ __nv_bfloat16 g_V2[24 * 2048 * 128];

#define QSC 0.18033688f   // 0.125 * log2(e)

// ================= helpers =================
__device__ __forceinline__ uint32_t smem_u32(const void* p) {
    uint32_t a;
    asm("{ .reg .u64 t; cvta.to.shared.u64 t, %1; cvt.u32.u64 %0, t; }" : "=r"(a) : "l"(p));
    return a;
}
__device__ __forceinline__ void ldsm4(uint32_t* r, uint32_t a) {
    asm volatile("ldmatrix.sync.aligned.m8n8.x4.shared.b16 {%0,%1,%2,%3}, [%4];"
                 : "=r"(r[0]), "=r"(r[1]), "=r"(r[2]), "=r"(r[3]) : "r"(a));
}
__device__ __forceinline__ void ldsm4t(uint32_t* r, uint32_t a) {
    asm volatile("ldmatrix.sync.aligned.m8n8.x4.trans.shared.b16 {%0,%1,%2,%3}, [%4];"
                 : "=r"(r[0]), "=r"(r[1]), "=r"(r[2]), "=r"(r[3]) : "r"(a));
}
__device__ __forceinline__ void mma16816(float* d, const uint32_t* a, uint32_t b0, uint32_t b1) {
    asm volatile("mma.sync.aligned.m16n8k16.row.col.f32.bf16.bf16.f32 "
                 "{%0,%1,%2,%3},{%4,%5,%6,%7},{%8,%9},{%0,%1,%2,%3};"
                 : "+f"(d[0]), "+f"(d[1]), "+f"(d[2]), "+f"(d[3])
                 : "r"(a[0]), "r"(a[1]), "r"(a[2]), "r"(a[3]), "r"(b0), "r"(b1));
}
__device__ __forceinline__ void cp16(uint32_t saddr, const void* gaddr) {
    asm volatile("cp.async.cg.shared.global [%0], [%1], 16;" :: "r"(saddr), "l"(gaddr));
}
__device__ __forceinline__ void cp_commit() { asm volatile("cp.async.commit_group;" ::: "memory"); }
__device__ __forceinline__ void cp_wait2()  { asm volatile("cp.async.wait_group 2;" ::: "memory"); }
__device__ __forceinline__ void cp_wait1()  { asm volatile("cp.async.wait_group 1;" ::: "memory"); }
__device__ __forceinline__ void cp_wait0()  { asm volatile("cp.async.wait_group 0;" ::: "memory"); }

__device__ __forceinline__ void split2(float x, float y, __nv_bfloat162& hi, __nv_bfloat162& lo) {
    hi = __float22bfloat162_rn(make_float2(x, y));
    float2 b = __bfloat1622float2(hi);
    lo = __float22bfloat162_rn(make_float2(x - b.x, y - b.y));
}

// ===== split-concat: f32 -> [R][3K] bf16 (GEMM operands) =====
__global__ void split3(const float* __restrict__ in, __nv_bfloat16* __restrict__ out,
                       int R, int K, int loMid) {
    int i = blockIdx.x * blockDim.x + threadIdx.x;
    int per_row = K >> 2;
    if (i >= R * per_row) return;
    int r = i / per_row, f = i % per_row;
    float4 v = *(const float4*)(in + (size_t)r * K + f * 4);
    __nv_bfloat162 H0, H1, L0, L1;
    split2(v.x, v.y, H0, L0);
    split2(v.z, v.w, H1, L1);
    __nv_bfloat16* o = out + (size_t)r * 3 * K + f * 4;
    ((__nv_bfloat162*)o)[0] = H0;  ((__nv_bfloat162*)o)[1] = H1;
    if (loMid) {
        ((__nv_bfloat162*)(o + K))[0] = L0;     ((__nv_bfloat162*)(o + K))[1] = L1;
        ((__nv_bfloat162*)(o + 2 * K))[0] = H0; ((__nv_bfloat162*)(o + 2 * K))[1] = H1;
    } else {
        ((__nv_bfloat162*)(o + K))[0] = H0;     ((__nv_bfloat162*)(o + K))[1] = H1;
        ((__nv_bfloat162*)(o + 2 * K))[0] = L0; ((__nv_bfloat162*)(o + 2 * K))[1] = L1;
    }
}

// ================= bf16 GEMM, 4-stage; optional fused per-head split output ============
__global__ __launch_bounds__(256, 2)
void mma_gemm(const __nv_bfloat16* __restrict__ A, const __nv_bfloat16* __restrict__ B,
              const float* __restrict__ bias, float* __restrict__ C,
              __nv_bfloat16* __restrict__ Q2o, __nv_bfloat16* __restrict__ K2o,
              __nv_bfloat16* __restrict__ V2o, int splitOut,
              int M, int N, int K3) {
    extern __shared__ char sm[];
    const uint32_t sb = smem_u32(sm);
    const int tid = threadIdx.x, wid = tid >> 5, lane = tid & 31;
    const int wm = wid & 3, wn = wid >> 2;
    const int mBase = blockIdx.y * 128, nBase = blockIdx.x * 128;
    const int NIT = K3 / 32;

    float acc[2][8][4] = {};

    auto load_stage = [&](int st, int k0) {
        uint32_t sA = sb + st * 20480, sB = sA + 10240;
#pragma unroll
        for (int i2 = 0; i2 < 2; i2++) {
            int c = tid + i2 * 256;
            int row = c >> 2, kc = c & 3;
            cp16(sA + row * 80 + kc * 16, A + (size_t)(mBase + row) * K3 + k0 + kc * 8);
            cp16(sB + row * 80 + kc * 16, B + (size_t)(nBase + row) * K3 + k0 + kc * 8);
        }
    };

    load_stage(0, 0);  cp_commit();
    load_stage(1, 32); cp_commit();
    load_stage(2, 64); cp_commit();

    for (int it = 0; it < NIT; it++) {
        cp_wait2();
        __syncthreads();
        if (it + 3 < NIT) { load_stage((it + 3) & 3, (it + 3) * 32); }
        cp_commit();

        uint32_t sA = sb + (it & 3) * 20480, sB = sA + 10240;
#pragma unroll
        for (int kk = 0; kk < 2; kk++) {
            uint32_t a[2][4], bq[4][4];
#pragma unroll
            for (int mt = 0; mt < 2; mt++)
                ldsm4(a[mt], sA + (wm * 32 + mt * 16 + (lane & 15)) * 80 + kk * 32 + (lane >> 4) * 16);
#pragma unroll
            for (int p = 0; p < 4; p++)
                ldsm4(bq[p], sB + (wn * 64 + p * 16 + (lane & 15)) * 80 + kk * 32 + (lane >> 4) * 16);
#pragma unroll
            for (int mt = 0; mt < 2; mt++)
#pragma unroll
                for (int nt = 0; nt < 8; nt++) {
                    int p = nt >> 1, j = nt & 1;
                    mma16816(acc[mt][nt], a[mt], bq[p][j], bq[p][j + 2]);
                }
        }
    }

    const int cbase = nBase + wn * 64;
#pragma unroll
    for (int nt = 0; nt < 8; nt++) {
        int col = cbase + nt * 8 + 2 * (lane & 3);
        float2 bv = *(const float2*)(bias + col);
#pragma unroll
        for (int mt = 0; mt < 2; mt++) {
            int r0 = mBase + wm * 32 + mt * 16 + (lane >> 2);
            float2 v0; v0.x = acc[mt][nt][0] + bv.x; v0.y = acc[mt][nt][1] + bv.y;
            float2 v1; v1.x = acc[mt][nt][2] + bv.x; v1.y = acc[mt][nt][3] + bv.y;
            if (!splitOut) {
                *(float2*)(C + (size_t)r0 * N + col) = v0;
                *(float2*)(C + (size_t)(r0 + 8) * N + col) = v1;
            } else {
                int m = col / 768;
                int hc = col - m * 768;
                int h = hc >> 6, d = hc & 63;
                __nv_bfloat16* base = (m == 0 ? Q2o : m == 1 ? K2o : V2o);
                float qs = (m == 0) ? QSC : 1.0f;
                __nv_bfloat162 H, L;
#pragma unroll
                for (int rr = 0; rr < 2; rr++) {
                    int r = r0 + rr * 8;
                    float2 v = rr ? v1 : v0;
                    split2(v.x * qs, v.y * qs, H, L);
                    __nv_bfloat16* dst = base +
                        ((size_t)((r >> 11) * 12 + h) * 2048 + (r & 2047)) * 128 + d;
                    *(__nv_bfloat162*)dst = H;
                    *(__nv_bfloat162*)(dst + 64) = L;
                }
            }
        }
    }
}

// ================= flash attention v7: kv-split across warp-halves ====================
// 512 threads. Warps 0-7: q-rows (wid&7)*16..+16, keys [0,1024). Warps 8-15: same rows,
// keys [1024,2048). Two independent 3-stage KV rings, lockstep kt (32 iters).
// Final merge of (m,l,O) halves through smem. Grid (16,24)=384 at 1 CTA/SM.
// Smem: Q 128x272 = 34816 @0 ; ring0 3x17920 @34816 ; ring1 3x17920 @88576 ; total 142336.
#define AT7_SMEM 142336

__device__ __forceinline__ void computeS(float (&sc)[4][4], uint32_t Qu, uint32_t Kst,
                                         int rw, int lane) {
#pragma unroll
    for (int nt = 0; nt < 4; nt++)
#pragma unroll
        for (int j = 0; j < 4; j++) sc[nt][j] = 0.f;
#pragma unroll
    for (int g = 0; g < 4; g++) {
        const uint32_t qrow = Qu + (rw * 16 + (lane & 15)) * 272 + g * 32 + (lane >> 4) * 16;
        const uint32_t krow0 = Kst + (lane & 15) * 272 + g * 32 + (lane >> 4) * 16;
        const uint32_t krow1 = Kst + (16 + (lane & 15)) * 272 + g * 32 + (lane >> 4) * 16;
        uint32_t aqh[4], aql[4], bh0[4], bh1[4], bl0[4], bl1[4];
        ldsm4(aqh, qrow);
        ldsm4(aql, qrow + 128);
        ldsm4(bh0, krow0);
        ldsm4(bh1, krow1);
        ldsm4(bl0, krow0 + 128);
        ldsm4(bl1, krow1 + 128);
        mma16816(sc[0], aqh, bh0[0], bh0[2]); mma16816(sc[1], aqh, bh0[1], bh0[3]);
        mma16816(sc[2], aqh, bh1[0], bh1[2]); mma16816(sc[3], aqh, bh1[1], bh1[3]);
        mma16816(sc[0], aql, bh0[0], bh0[2]); mma16816(sc[1], aql, bh0[1], bh0[3]);
        mma16816(sc[2], aql, bh1[0], bh1[2]); mma16816(sc[3], aql, bh1[1], bh1[3]);
        mma16816(sc[0], aqh, bl0[0], bl0[2]); mma16816(sc[1], aqh, bl0[1], bl0[3]);
        mma16816(sc[2], aqh, bl1[0], bl1[2]); mma16816(sc[3], aqh, bl1[1], bl1[3]);
    }
}

__global__ __launch_bounds__(512, 1)
void attn7(const __nv_bfloat16* __restrict__ Q2, const __nv_bfloat16* __restrict__ K2,
           const __nv_bfloat16* __restrict__ V2, __nv_bfloat16* __restrict__ A2) {
    extern __shared__ char sm[];
    const uint32_t sb = smem_u32(sm);
    const uint32_t Qu = sb;

    const int tid = threadIdx.x, wid = tid >> 5, lane = tid & 31;
    const int rw = wid & 7, half = wid >> 3;
    const int bh = blockIdx.y;
    const int q0 = blockIdx.x * 128;

    const __nv_bfloat16* Qg = Q2 + ((size_t)bh * 2048 + q0) * 128;
    const __nv_bfloat16* Kg[2] = { K2 + (size_t)bh * 2048 * 128,
                                   K2 + ((size_t)bh * 2048 + 1024) * 128 };
    const __nv_bfloat16* Vg[2] = { V2 + (size_t)bh * 2048 * 128,
                                   V2 + ((size_t)bh * 2048 + 1024) * 128 };

    auto stageK = [&](int h, int st) { return sb + 34816 + h * 53760 + st * 17920; };

    auto loadKV = [&](int st, int kt) {
#pragma unroll
        for (int r = 0; r < 2; r++) {
            uint32_t Ku = stageK(r, st), Vu = Ku + 8704;
            // K: 32 rows x 16 chunks = 512 chunks, 1 per thread
            int krow = tid >> 4, kj = tid & 15;
            cp16(Ku + krow * 272 + kj * 16,
                 Kg[r] + (size_t)kt * 32 * 128 + krow * 128 + kj * 8);
            // V: 64 rows x 8 chunks = 512 chunks, 1 per thread
            int vrow = tid >> 3, vj = tid & 7;
            cp16(Vu + vrow * 144 + vj * 16,
                 Vg[r] + (size_t)kt * 32 * 128 + (vrow & 31) * 128 + (vrow >> 5) * 64 + vj * 8);
        }
    };

    // prologue: Q (2048 chunks / 512 thr = 4 each) + KV0, KV1
#pragma unroll
    for (int i = 0; i < 4; i++) {
        int idx = tid + i * 512;
        int row = idx >> 4, j = idx & 15;
        cp16(Qu + row * 272 + j * 16, Qg + row * 128 + j * 8);
    }
    loadKV(0, 0);
    cp_commit();
    loadKV(1, 1);
    cp_commit();
    cp_wait1();
    __syncthreads();

    float oc[8][4] = {};
    float mrow[2] = { -1e30f, -1e30f };
    float lrow[2] = { 0.f, 0.f };
    float sc0[4][4], sc1[4][4];

    computeS(sc0, Qu, stageK(half, 0), rw, lane);

    auto body = [&](float (&scCur)[4][4], float (&scNxt)[4][4], int kt) {
        __syncthreads();
        if (kt + 2 < 32) {
            loadKV((kt + 2) % 3, kt + 2);
            cp_commit();
            cp_wait1();
        } else {
            cp_wait0();
        }
        __syncthreads();

        if (kt + 1 < 32)
            computeS(scNxt, Qu, stageK(half, (kt + 1) % 3), rw, lane);

        // ---- softmax(kt) (base-2 domain, Q pre-scaled) ----
        float m0 = -1e30f, m1 = -1e30f;
#pragma unroll
        for (int nt = 0; nt < 4; nt++) {
            m0 = fmaxf(m0, fmaxf(scCur[nt][0], scCur[nt][1]));
            m1 = fmaxf(m1, fmaxf(scCur[nt][2], scCur[nt][3]));
        }
        m0 = fmaxf(m0, __shfl_xor_sync(0xffffffffu, m0, 1));
        m0 = fmaxf(m0, __shfl_xor_sync(0xffffffffu, m0, 2));
        m1 = fmaxf(m1, __shfl_xor_sync(0xffffffffu, m1, 1));
        m1 = fmaxf(m1, __shfl_xor_sync(0xffffffffu, m1, 2));
        float mn0 = fmaxf(mrow[0], m0), mn1 = fmaxf(mrow[1], m1);
        float al0 = exp2f(mrow[0] - mn0), al1 = exp2f(mrow[1] - mn1);
        mrow[0] = mn0; mrow[1] = mn1;

        float s0 = 0.f, s1 = 0.f;
#pragma unroll
        for (int nt = 0; nt < 4; nt++) {
            scCur[nt][0] = exp2f(scCur[nt][0] - mn0);
            scCur[nt][1] = exp2f(scCur[nt][1] - mn0);
            scCur[nt][2] = exp2f(scCur[nt][2] - mn1);
            scCur[nt][3] = exp2f(scCur[nt][3] - mn1);
            s0 += scCur[nt][0] + scCur[nt][1];
            s1 += scCur[nt][2] + scCur[nt][3];
        }
        s0 += __shfl_xor_sync(0xffffffffu, s0, 1);
        s0 += __shfl_xor_sync(0xffffffffu, s0, 2);
        s1 += __shfl_xor_sync(0xffffffffu, s1, 1);
        s1 += __shfl_xor_sync(0xffffffffu, s1, 2);
        lrow[0] = lrow[0] * al0 + s0;
        lrow[1] = lrow[1] * al1 + s1;

#pragma unroll
        for (int nt = 0; nt < 8; nt++) {
            oc[nt][0] *= al0; oc[nt][1] *= al0;
            oc[nt][2] *= al1; oc[nt][3] *= al1;
        }

        // ---- PV(kt) ----
        const uint32_t Vst = stageK(half, kt % 3) + 8704;
#pragma unroll
        for (int kg = 0; kg < 2; kg++) {
            uint32_t Ph[4], Pl[4];
#pragma unroll
            for (int e = 0; e < 2; e++) {
                const float* f0 = scCur[kg * 2];
                const float* f1 = scCur[kg * 2 + 1];
                __nv_bfloat162 H, L;
                split2(f0[e * 2], f0[e * 2 + 1], H, L);
                Ph[e] = *(uint32_t*)&H; Pl[e] = *(uint32_t*)&L;
                split2(f1[e * 2], f1[e * 2 + 1], H, L);
                Ph[e + 2] = *(uint32_t*)&H; Pl[e + 2] = *(uint32_t*)&L;
            }
#pragma unroll
            for (int vt = 0; vt < 2; vt++) {
                uint32_t bv[4][4];
#pragma unroll
                for (int p = 0; p < 4; p++)
                    ldsm4t(bv[p], Vst + (vt * 32 + kg * 16 + (lane & 15)) * 144 +
                                   p * 32 + (lane >> 4) * 16);
#pragma unroll
                for (int p = 0; p < 4; p++)
#pragma unroll
                    for (int j = 0; j < 2; j++) {
                        mma16816(oc[p * 2 + j], Ph, bv[p][j * 2], bv[p][j * 2 + 1]);
                        if (vt == 0)
                            mma16816(oc[p * 2 + j], Pl, bv[p][j * 2], bv[p][j * 2 + 1]);
                    }
            }
        }
    };

    for (int kt = 0; kt < 32; kt += 2) {
        body(sc0, sc1, kt);
        body(sc1, sc0, kt + 1);
    }

    // ---- merge halves (reuse ring smem), then write A2 [hi|lo|hi] ----
    float* Ob = (float*)(sm + 34816);                 // [8][32][32] f32 = 32KB
    float* Ml = (float*)(sm + 34816 + 32768);         // [8][32][4]  f32 = 4KB
    __syncthreads();
    if (half == 1) {
        float* ob = Ob + (rw * 32 + lane) * 32;
#pragma unroll
        for (int nt = 0; nt < 8; nt++) {
            ob[nt * 4 + 0] = oc[nt][0]; ob[nt * 4 + 1] = oc[nt][1];
            ob[nt * 4 + 2] = oc[nt][2]; ob[nt * 4 + 3] = oc[nt][3];
        }
        float* ml = Ml + (rw * 32 + lane) * 4;
        ml[0] = mrow[0]; ml[1] = mrow[1]; ml[2] = lrow[0]; ml[3] = lrow[1];
    }
    __syncthreads();
    if (half == 0) {
        const float* ob = Ob + (rw * 32 + lane) * 32;
        const float* ml = Ml + (rw * 32 + lane) * 4;
        float pm0 = ml[0], pm1 = ml[1], pl0 = ml[2], pl1 = ml[3];
        float mm0 = fmaxf(mrow[0], pm0), mm1 = fmaxf(mrow[1], pm1);
        float a10 = exp2f(mrow[0] - mm0), a20 = exp2f(pm0 - mm0);
        float a11 = exp2f(mrow[1] - mm1), a21 = exp2f(pm1 - mm1);
        float i0 = 1.0f / (lrow[0] * a10 + pl0 * a20);
        float i1 = 1.0f / (lrow[1] * a11 + pl1 * a21);

        int b = bh / 12, h = bh % 12;
        int r = b * 2048 + q0 + rw * 16 + (lane >> 2);
#pragma unroll
        for (int nt = 0; nt < 8; nt++) {
            int c = h * 64 + nt * 8 + 2 * (lane & 3);
            float o0 = (oc[nt][0] * a10 + ob[nt * 4 + 0] * a20) * i0;
            float o1 = (oc[nt][1] * a10 + ob[nt * 4 + 1] * a20) * i0;
            float o2 = (oc[nt][2] * a11 + ob[nt * 4 + 2] * a21) * i1;
            float o3 = (oc[nt][3] * a11 + ob[nt * 4 + 3] * a21) * i1;
            __nv_bfloat162 H, L;
            split2(o0, o1, H, L);
            __nv_bfloat16* base = A2 + (size_t)r * 2304 + c;
            *(__nv_bfloat162*)base = H;
            *(__nv_bfloat162*)(base + 768) = L;
            *(__nv_bfloat162*)(base + 1536) = H;
            split2(o2, o3, H, L);
            base = A2 + (size_t)(r + 8) * 2304 + c;
            *(__nv_bfloat162*)base = H;
            *(__nv_bfloat162*)(base + 768) = L;
            *(__nv_bfloat162*)(base + 1536) = H;
        }
    }
}

// ---------------- launch ----------------
extern "C" void kernel_launch(void* const* d_in, const int* in_sizes, int n_in,
                              void* d_out, int out_size) {
    const float* x      = (const float*)d_in[0];
    const float* qkv_w  = (const float*)d_in[1];
    const float* qkv_b  = (const float*)d_in[2];
    const float* proj_w = (const float*)d_in[3];
    const float* proj_b = (const float*)d_in[4];
    float* out = (float*)d_out;

    __nv_bfloat16 *A2, *B1, *B2, *Q2, *K2, *V2;
    cudaGetSymbolAddress((void**)&A2,  g_A2);
    cudaGetSymbolAddress((void**)&B1,  g_B1);
    cudaGetSymbolAddress((void**)&B2,  g_B2);
    cudaGetSymbolAddress((void**)&Q2,  g_Q2);
    cudaGetSymbolAddress((void**)&K2,  g_K2);
    cudaGetSymbolAddress((void**)&V2,  g_V2);

    const int gemm_smem = 4 * 20480;
    cudaFuncSetAttribute(mma_gemm, cudaFuncAttributeMaxDynamicSharedMemorySize, gemm_smem);
    cudaFuncSetAttribute(attn7, cudaFuncAttributeMaxDynamicSharedMemorySize, AT7_SMEM);

    split3<<<(4096 * 192 + 255) / 256, 256>>>(x, A2, 4096, 768, 1);
    split3<<<(2304 * 192 + 255) / 256, 256>>>(qkv_w, B1, 2304, 768, 0);

    // 1) qkv GEMM with fused per-head hi/lo split output (Q pre-scaled by QSC)
    mma_gemm<<<dim3(18, 32), 256, gemm_smem>>>(A2, B1, qkv_b, nullptr,
                                               Q2, K2, V2, 1, 4096, 2304, 2304);

    // 2) attention -> A2 ([hi|lo|hi] split, ready for proj GEMM)
    attn7<<<dim3(16, 24), 512, AT7_SMEM>>>(Q2, K2, V2, A2);

    split3<<<(768 * 192 + 255) / 256, 256>>>(proj_w, B2, 768, 768, 0);

    // 3) out = ao @ proj_w^T + proj_b
    mma_gemm<<<dim3(6, 32), 256, gemm_smem>>>(A2, B2, proj_b, out,
                                              nullptr, nullptr, nullptr, 0, 4096, 768, 2304);
}

// round 12
// speedup vs baseline: 1.0442x; 1.0442x over previous
#include <cuda_runtime.h>
#include <cuda_bf16.h>
#include <cstdint>

// ---------------- scratch (no cudaMalloc allowed) ----------------
__device__ __nv_bfloat16 g_A2[4096 * 2304];          // x-split, later ao-split [hi|lo|hi]
__device__ __nv_bfloat16 g_B1[2304 * 2304];          // qkv_w split [hi|hi|lo]
__device__ __nv_bfloat16 g_B2[768 * 2304];           // proj_w split [hi|hi|lo]
__device__ __nv_bfloat16 g_Q2[24 * 2048 * 128];      // per-head hi|lo (Q pre-scaled)
__device__ __nv_bfloat16 g_K2[24 * 2048 * 128];
__device__ __nv_bfloat16 g_V2[24 * 2048 * 128];
__device__ float g_Op[2 * 24 * 2048 * 64];           // partial O  [half][bh][row][d]
__device__ float g_Ml[2 * 24 * 2048 * 2];            // partial m,l [half][bh][row]

#define QSC 0.18033688f   // 0.125 * log2(e)

// ================= helpers =================
__device__ __forceinline__ uint32_t smem_u32(const void* p) {
    uint32_t a;
    asm("{ .reg .u64 t; cvta.to.shared.u64 t, %1; cvt.u32.u64 %0, t; }" : "=r"(a) : "l"(p));
    return a;
}
__device__ __forceinline__ void ldsm4(uint32_t* r, uint32_t a) {
    asm volatile("ldmatrix.sync.aligned.m8n8.x4.shared.b16 {%0,%1,%2,%3}, [%4];"
                 : "=r"(r[0]), "=r"(r[1]), "=r"(r[2]), "=r"(r[3]) : "r"(a));
}
__device__ __forceinline__ void ldsm4t(uint32_t* r, uint32_t a) {
    asm volatile("ldmatrix.sync.aligned.m8n8.x4.trans.shared.b16 {%0,%1,%2,%3}, [%4];"
                 : "=r"(r[0]), "=r"(r[1]), "=r"(r[2]), "=r"(r[3]) : "r"(a));
}
__device__ __forceinline__ void mma16816(float* d, const uint32_t* a, uint32_t b0, uint32_t b1) {
    asm volatile("mma.sync.aligned.m16n8k16.row.col.f32.bf16.bf16.f32 "
                 "{%0,%1,%2,%3},{%4,%5,%6,%7},{%8,%9},{%0,%1,%2,%3};"
                 : "+f"(d[0]), "+f"(d[1]), "+f"(d[2]), "+f"(d[3])
                 : "r"(a[0]), "r"(a[1]), "r"(a[2]), "r"(a[3]), "r"(b0), "r"(b1));
}
__device__ __forceinline__ void cp16(uint32_t saddr, const void* gaddr) {
    asm volatile("cp.async.cg.shared.global [%0], [%1], 16;" :: "r"(saddr), "l"(gaddr));
}
__device__ __forceinline__ void cp_commit() { asm volatile("cp.async.commit_group;" ::: "memory"); }
__device__ __forceinline__ void cp_wait2()  { asm volatile("cp.async.wait_group 2;" ::: "memory"); }
__device__ __forceinline__ void cp_wait1()  { asm volatile("cp.async.wait_group 1;" ::: "memory"); }
__device__ __forceinline__ void cp_wait0()  { asm volatile("cp.async.wait_group 0;" ::: "memory"); }

__device__ __forceinline__ void split2(float x, float y, __nv_bfloat162& hi, __nv_bfloat162& lo) {
    hi = __float22bfloat162_rn(make_float2(x, y));
    float2 b = __bfloat1622float2(hi);
    lo = __float22bfloat162_rn(make_float2(x - b.x, y - b.y));
}

// ===== split-concat: f32 -> [R][3K] bf16 (GEMM operands) =====
__global__ void split3(const float* __restrict__ in, __nv_bfloat16* __restrict__ out,
                       int R, int K, int loMid) {
    int i = blockIdx.x * blockDim.x + threadIdx.x;
    int per_row = K >> 2;
    if (i >= R * per_row) return;
    int r = i / per_row, f = i % per_row;
    float4 v = *(const float4*)(in + (size_t)r * K + f * 4);
    __nv_bfloat162 H0, H1, L0, L1;
    split2(v.x, v.y, H0, L0);
    split2(v.z, v.w, H1, L1);
    __nv_bfloat16* o = out + (size_t)r * 3 * K + f * 4;
    ((__nv_bfloat162*)o)[0] = H0;  ((__nv_bfloat162*)o)[1] = H1;
    if (loMid) {
        ((__nv_bfloat162*)(o + K))[0] = L0;     ((__nv_bfloat162*)(o + K))[1] = L1;
        ((__nv_bfloat162*)(o + 2 * K))[0] = H0; ((__nv_bfloat162*)(o + 2 * K))[1] = H1;
    } else {
        ((__nv_bfloat162*)(o + K))[0] = H0;     ((__nv_bfloat162*)(o + K))[1] = H1;
        ((__nv_bfloat162*)(o + 2 * K))[0] = L0; ((__nv_bfloat162*)(o + 2 * K))[1] = L1;
    }
}

// ================= bf16 GEMM, 4-stage; optional fused per-head split output ============
__global__ __launch_bounds__(256, 2)
void mma_gemm(const __nv_bfloat16* __restrict__ A, const __nv_bfloat16* __restrict__ B,
              const float* __restrict__ bias, float* __restrict__ C,
              __nv_bfloat16* __restrict__ Q2o, __nv_bfloat16* __restrict__ K2o,
              __nv_bfloat16* __restrict__ V2o, int splitOut,
              int M, int N, int K3) {
    extern __shared__ char sm[];
    const uint32_t sb = smem_u32(sm);
    const int tid = threadIdx.x, wid = tid >> 5, lane = tid & 31;
    const int wm = wid & 3, wn = wid >> 2;
    const int mBase = blockIdx.y * 128, nBase = blockIdx.x * 128;
    const int NIT = K3 / 32;

    float acc[2][8][4] = {};

    auto load_stage = [&](int st, int k0) {
        uint32_t sA = sb + st * 20480, sB = sA + 10240;
#pragma unroll
        for (int i2 = 0; i2 < 2; i2++) {
            int c = tid + i2 * 256;
            int row = c >> 2, kc = c & 3;
            cp16(sA + row * 80 + kc * 16, A + (size_t)(mBase + row) * K3 + k0 + kc * 8);
            cp16(sB + row * 80 + kc * 16, B + (size_t)(nBase + row) * K3 + k0 + kc * 8);
        }
    };

    load_stage(0, 0);  cp_commit();
    load_stage(1, 32); cp_commit();
    load_stage(2, 64); cp_commit();

    for (int it = 0; it < NIT; it++) {
        cp_wait2();
        __syncthreads();
        if (it + 3 < NIT) { load_stage((it + 3) & 3, (it + 3) * 32); }
        cp_commit();

        uint32_t sA = sb + (it & 3) * 20480, sB = sA + 10240;
#pragma unroll
        for (int kk = 0; kk < 2; kk++) {
            uint32_t a[2][4], bq[4][4];
#pragma unroll
            for (int mt = 0; mt < 2; mt++)
                ldsm4(a[mt], sA + (wm * 32 + mt * 16 + (lane & 15)) * 80 + kk * 32 + (lane >> 4) * 16);
#pragma unroll
            for (int p = 0; p < 4; p++)
                ldsm4(bq[p], sB + (wn * 64 + p * 16 + (lane & 15)) * 80 + kk * 32 + (lane >> 4) * 16);
#pragma unroll
            for (int mt = 0; mt < 2; mt++)
#pragma unroll
                for (int nt = 0; nt < 8; nt++) {
                    int p = nt >> 1, j = nt & 1;
                    mma16816(acc[mt][nt], a[mt], bq[p][j], bq[p][j + 2]);
                }
        }
    }

    const int cbase = nBase + wn * 64;
#pragma unroll
    for (int nt = 0; nt < 8; nt++) {
        int col = cbase + nt * 8 + 2 * (lane & 3);
        float2 bv = *(const float2*)(bias + col);
#pragma unroll
        for (int mt = 0; mt < 2; mt++) {
            int r0 = mBase + wm * 32 + mt * 16 + (lane >> 2);
            float2 v0; v0.x = acc[mt][nt][0] + bv.x; v0.y = acc[mt][nt][1] + bv.y;
            float2 v1; v1.x = acc[mt][nt][2] + bv.x; v1.y = acc[mt][nt][3] + bv.y;
            if (!splitOut) {
                *(float2*)(C + (size_t)r0 * N + col) = v0;
                *(float2*)(C + (size_t)(r0 + 8) * N + col) = v1;
            } else {
                int m = col / 768;
                int hc = col - m * 768;
                int h = hc >> 6, d = hc & 63;
                __nv_bfloat16* base = (m == 0 ? Q2o : m == 1 ? K2o : V2o);
                float qs = (m == 0) ? QSC : 1.0f;
                __nv_bfloat162 H, L;
#pragma unroll
                for (int rr = 0; rr < 2; rr++) {
                    int r = r0 + rr * 8;
                    float2 v = rr ? v1 : v0;
                    split2(v.x * qs, v.y * qs, H, L);
                    __nv_bfloat16* dst = base +
                        ((size_t)((r >> 11) * 12 + h) * 2048 + (r & 2047)) * 128 + d;
                    *(__nv_bfloat162*)dst = H;
                    *(__nv_bfloat162*)(dst + 64) = L;
                }
            }
        }
    }
}

// ================= flash attention v8: attn6 structure, kv-half per CTA ================
// Grid (16, 24, 2): blockIdx.z selects keys [z*1024, z*1024+1024). 32 iterations.
// Partial fp32 (O, m, l) to global; merged by mergeO. 2 CTAs/SM preserved.
#define AT8_SMEM (34816 + 3 * 17920)   // 88576

__device__ __forceinline__ void computeS(float (&sc)[4][4], uint32_t Qu, uint32_t Kst,
                                         int wid, int lane) {
#pragma unroll
    for (int nt = 0; nt < 4; nt++)
#pragma unroll
        for (int j = 0; j < 4; j++) sc[nt][j] = 0.f;
#pragma unroll
    for (int g = 0; g < 4; g++) {
        const uint32_t qrow = Qu + (wid * 16 + (lane & 15)) * 272 + g * 32 + (lane >> 4) * 16;
        const uint32_t krow0 = Kst + (lane & 15) * 272 + g * 32 + (lane >> 4) * 16;
        const uint32_t krow1 = Kst + (16 + (lane & 15)) * 272 + g * 32 + (lane >> 4) * 16;
        uint32_t aqh[4], aql[4], bh0[4], bh1[4], bl0[4], bl1[4];
        ldsm4(aqh, qrow);
        ldsm4(aql, qrow + 128);
        ldsm4(bh0, krow0);
        ldsm4(bh1, krow1);
        ldsm4(bl0, krow0 + 128);
        ldsm4(bl1, krow1 + 128);
        mma16816(sc[0], aqh, bh0[0], bh0[2]); mma16816(sc[1], aqh, bh0[1], bh0[3]);
        mma16816(sc[2], aqh, bh1[0], bh1[2]); mma16816(sc[3], aqh, bh1[1], bh1[3]);
        mma16816(sc[0], aql, bh0[0], bh0[2]); mma16816(sc[1], aql, bh0[1], bh0[3]);
        mma16816(sc[2], aql, bh1[0], bh1[2]); mma16816(sc[3], aql, bh1[1], bh1[3]);
        mma16816(sc[0], aqh, bl0[0], bl0[2]); mma16816(sc[1], aqh, bl0[1], bl0[3]);
        mma16816(sc[2], aqh, bl1[0], bl1[2]); mma16816(sc[3], aqh, bl1[1], bl1[3]);
    }
}

__global__ __launch_bounds__(256, 2)
void attn8(const __nv_bfloat16* __restrict__ Q2, const __nv_bfloat16* __restrict__ K2,
           const __nv_bfloat16* __restrict__ V2, float* __restrict__ Op,
           float* __restrict__ Ml) {
    extern __shared__ char sm[];
    const uint32_t sb = smem_u32(sm);
    const uint32_t Qu = sb;

    const int tid = threadIdx.x, wid = tid >> 5, lane = tid & 31;
    const int bh = blockIdx.y;
    const int q0 = blockIdx.x * 128;
    const int half = blockIdx.z;

    const __nv_bfloat16* Qg = Q2 + ((size_t)bh * 2048 + q0) * 128;
    const __nv_bfloat16* Kg0 = K2 + ((size_t)bh * 2048 + half * 1024) * 128;
    const __nv_bfloat16* Vg0 = V2 + ((size_t)bh * 2048 + half * 1024) * 128;

    auto stageK = [&](int st) { return sb + 34816 + st * 17920; };

    auto loadKV = [&](int st, int kt) {
        const __nv_bfloat16* Kg = Kg0 + (size_t)kt * 32 * 128;
        const __nv_bfloat16* Vg = Vg0 + (size_t)kt * 32 * 128;
        uint32_t Ku = stageK(st), Vu = Ku + 8704;
#pragma unroll
        for (int i = 0; i < 2; i++) {
            int idx = tid + i * 256;
            int row = idx >> 4, j = idx & 15;
            cp16(Ku + row * 272 + j * 16, Kg + row * 128 + j * 8);
        }
#pragma unroll
        for (int i = 0; i < 2; i++) {
            int idx = tid + i * 256;
            int row = idx >> 3, j = idx & 7;
            cp16(Vu + row * 144 + j * 16,
                 Vg + (row & 31) * 128 + (row >> 5) * 64 + j * 8);
        }
    };

#pragma unroll
    for (int i = 0; i < 8; i++) {
        int idx = tid + i * 256;
        int row = idx >> 4, j = idx & 15;
        cp16(Qu + row * 272 + j * 16, Qg + row * 128 + j * 8);
    }
    loadKV(0, 0);
    cp_commit();
    loadKV(1, 1);
    cp_commit();
    cp_wait1();
    __syncthreads();

    float oc[8][4] = {};
    float mrow[2] = { -1e30f, -1e30f };
    float lrow[2] = { 0.f, 0.f };
    float sc0[4][4], sc1[4][4];

    computeS(sc0, Qu, stageK(0), wid, lane);

    auto body = [&](float (&scCur)[4][4], float (&scNxt)[4][4], int kt) {
        __syncthreads();
        if (kt + 2 < 32) {
            loadKV((kt + 2) % 3, kt + 2);
            cp_commit();
            cp_wait1();
        } else {
            cp_wait0();
        }
        __syncthreads();

        if (kt + 1 < 32)
            computeS(scNxt, Qu, stageK((kt + 1) % 3), wid, lane);

        float m0 = -1e30f, m1 = -1e30f;
#pragma unroll
        for (int nt = 0; nt < 4; nt++) {
            m0 = fmaxf(m0, fmaxf(scCur[nt][0], scCur[nt][1]));
            m1 = fmaxf(m1, fmaxf(scCur[nt][2], scCur[nt][3]));
        }
        m0 = fmaxf(m0, __shfl_xor_sync(0xffffffffu, m0, 1));
        m0 = fmaxf(m0, __shfl_xor_sync(0xffffffffu, m0, 2));
        m1 = fmaxf(m1, __shfl_xor_sync(0xffffffffu, m1, 1));
        m1 = fmaxf(m1, __shfl_xor_sync(0xffffffffu, m1, 2));
        float mn0 = fmaxf(mrow[0], m0), mn1 = fmaxf(mrow[1], m1);
        float al0 = exp2f(mrow[0] - mn0), al1 = exp2f(mrow[1] - mn1);
        mrow[0] = mn0; mrow[1] = mn1;

        float s0 = 0.f, s1 = 0.f;
#pragma unroll
        for (int nt = 0; nt < 4; nt++) {
            scCur[nt][0] = exp2f(scCur[nt][0] - mn0);
            scCur[nt][1] = exp2f(scCur[nt][1] - mn0);
            scCur[nt][2] = exp2f(scCur[nt][2] - mn1);
            scCur[nt][3] = exp2f(scCur[nt][3] - mn1);
            s0 += scCur[nt][0] + scCur[nt][1];
            s1 += scCur[nt][2] + scCur[nt][3];
        }
        s0 += __shfl_xor_sync(0xffffffffu, s0, 1);
        s0 += __shfl_xor_sync(0xffffffffu, s0, 2);
        s1 += __shfl_xor_sync(0xffffffffu, s1, 1);
        s1 += __shfl_xor_sync(0xffffffffu, s1, 2);
        lrow[0] = lrow[0] * al0 + s0;
        lrow[1] = lrow[1] * al1 + s1;

#pragma unroll
        for (int nt = 0; nt < 8; nt++) {
            oc[nt][0] *= al0; oc[nt][1] *= al0;
            oc[nt][2] *= al1; oc[nt][3] *= al1;
        }

        const uint32_t Vst = stageK(kt % 3) + 8704;
#pragma unroll
        for (int kg = 0; kg < 2; kg++) {
            uint32_t Ph[4], Pl[4];
#pragma unroll
            for (int e = 0; e < 2; e++) {
                const float* f0 = scCur[kg * 2];
                const float* f1 = scCur[kg * 2 + 1];
                __nv_bfloat162 H, L;
                split2(f0[e * 2], f0[e * 2 + 1], H, L);
                Ph[e] = *(uint32_t*)&H; Pl[e] = *(uint32_t*)&L;
                split2(f1[e * 2], f1[e * 2 + 1], H, L);
                Ph[e + 2] = *(uint32_t*)&H; Pl[e + 2] = *(uint32_t*)&L;
            }
#pragma unroll
            for (int vt = 0; vt < 2; vt++) {
                uint32_t bv[4][4];
#pragma unroll
                for (int p = 0; p < 4; p++)
                    ldsm4t(bv[p], Vst + (vt * 32 + kg * 16 + (lane & 15)) * 144 +
                                   p * 32 + (lane >> 4) * 16);
#pragma unroll
                for (int p = 0; p < 4; p++)
#pragma unroll
                    for (int j = 0; j < 2; j++) {
                        mma16816(oc[p * 2 + j], Ph, bv[p][j * 2], bv[p][j * 2 + 1]);
                        if (vt == 0)
                            mma16816(oc[p * 2 + j], Pl, bv[p][j * 2], bv[p][j * 2 + 1]);
                    }
            }
        }
    };

    for (int kt = 0; kt < 32; kt += 2) {
        body(sc0, sc1, kt);
        body(sc1, sc0, kt + 1);
    }

    // ---- epilogue: partial fp32 O, m, l ----
    {
        int r = q0 + wid * 16 + (lane >> 2);
        size_t rbase = ((size_t)(half * 24 + bh) * 2048 + r);
        float* op0 = Op + rbase * 64;
        float* op1 = Op + (rbase + 8) * 64;
#pragma unroll
        for (int nt = 0; nt < 8; nt++) {
            int c = nt * 8 + 2 * (lane & 3);
            *(float2*)(op0 + c) = make_float2(oc[nt][0], oc[nt][1]);
            *(float2*)(op1 + c) = make_float2(oc[nt][2], oc[nt][3]);
        }
        if ((lane & 3) == 0) {
            *(float2*)(Ml + rbase * 2) = make_float2(mrow[0], lrow[0]);
            *(float2*)(Ml + (rbase + 8) * 2) = make_float2(mrow[1], lrow[1]);
        }
    }
}

// ===== merge halves -> A2 [hi|lo|hi] =====
__global__ void mergeO(const float* __restrict__ Op, const float* __restrict__ Ml,
                       __nv_bfloat16* __restrict__ A2) {
    int i = blockIdx.x * blockDim.x + threadIdx.x;
    if (i >= 24 * 2048 * 8) return;
    int cg = i & 7;
    int row = (i >> 3) & 2047;
    int bh = i >> 14;
    int b = bh / 12, h = bh % 12;

    size_t r1 = (size_t)bh * 2048 + row;
    size_t r2 = (size_t)(24 + bh) * 2048 + row;
    float2 ml1 = *(const float2*)(Ml + r1 * 2);
    float2 ml2 = *(const float2*)(Ml + r2 * 2);
    float mm = fmaxf(ml1.x, ml2.x);
    float a1 = exp2f(ml1.x - mm), a2 = exp2f(ml2.x - mm);
    float inv = 1.0f / (ml1.y * a1 + ml2.y * a2);
    a1 *= inv; a2 *= inv;

    const float* o1 = Op + r1 * 64 + cg * 8;
    const float* o2 = Op + r2 * 64 + cg * 8;
    float4 p1a = *(const float4*)o1, p1b = *(const float4*)(o1 + 4);
    float4 p2a = *(const float4*)o2, p2b = *(const float4*)(o2 + 4);

    float v[8];
    v[0] = p1a.x * a1 + p2a.x * a2; v[1] = p1a.y * a1 + p2a.y * a2;
    v[2] = p1a.z * a1 + p2a.z * a2; v[3] = p1a.w * a1 + p2a.w * a2;
    v[4] = p1b.x * a1 + p2b.x * a2; v[5] = p1b.y * a1 + p2b.y * a2;
    v[6] = p1b.z * a1 + p2b.z * a2; v[7] = p1b.w * a1 + p2b.w * a2;

    __nv_bfloat16* base = A2 + (size_t)(b * 2048 + row) * 2304 + h * 64 + cg * 8;
#pragma unroll
    for (int j = 0; j < 8; j += 2) {
        __nv_bfloat162 H, L;
        split2(v[j], v[j + 1], H, L);
        *(__nv_bfloat162*)(base + j) = H;
        *(__nv_bfloat162*)(base + 768 + j) = L;
        *(__nv_bfloat162*)(base + 1536 + j) = H;
    }
}

// ---------------- launch ----------------
extern "C" void kernel_launch(void* const* d_in, const int* in_sizes, int n_in,
                              void* d_out, int out_size) {
    const float* x      = (const float*)d_in[0];
    const float* qkv_w  = (const float*)d_in[1];
    const float* qkv_b  = (const float*)d_in[2];
    const float* proj_w = (const float*)d_in[3];
    const float* proj_b = (const float*)d_in[4];
    float* out = (float*)d_out;

    __nv_bfloat16 *A2, *B1, *B2, *Q2, *K2, *V2;
    float *Op, *Ml;
    cudaGetSymbolAddress((void**)&A2,  g_A2);
    cudaGetSymbolAddress((void**)&B1,  g_B1);
    cudaGetSymbolAddress((void**)&B2,  g_B2);
    cudaGetSymbolAddress((void**)&Q2,  g_Q2);
    cudaGetSymbolAddress((void**)&K2,  g_K2);
    cudaGetSymbolAddress((void**)&V2,  g_V2);
    cudaGetSymbolAddress((void**)&Op,  g_Op);
    cudaGetSymbolAddress((void**)&Ml,  g_Ml);

    const int gemm_smem = 4 * 20480;
    cudaFuncSetAttribute(mma_gemm, cudaFuncAttributeMaxDynamicSharedMemorySize, gemm_smem);
    cudaFuncSetAttribute(attn8, cudaFuncAttributeMaxDynamicSharedMemorySize, AT8_SMEM);

    split3<<<(4096 * 192 + 255) / 256, 256>>>(x, A2, 4096, 768, 1);
    split3<<<(2304 * 192 + 255) / 256, 256>>>(qkv_w, B1, 2304, 768, 0);

    // 1) qkv GEMM with fused per-head hi/lo split output (Q pre-scaled by QSC)
    mma_gemm<<<dim3(18, 32), 256, gemm_smem>>>(A2, B1, qkv_b, nullptr,
                                               Q2, K2, V2, 1, 4096, 2304, 2304);

    // 2) attention: kv-split halves -> partial (O,m,l), then merge -> A2
    attn8<<<dim3(16, 24, 2), 256, AT8_SMEM>>>(Q2, K2, V2, Op, Ml);
    mergeO<<<(24 * 2048 * 8 + 255) / 256, 256>>>(Op, Ml, A2);

    split3<<<(768 * 192 + 255) / 256, 256>>>(proj_w, B2, 768, 768, 0);

    // 3) out = ao @ proj_w^T + proj_b
    mma_gemm<<<dim3(6, 32), 256, gemm_smem>>>(A2, B2, proj_b, out,
                                              nullptr, nullptr, nullptr, 0, 4096, 768, 2304);
}

// round 13
// speedup vs baseline: 1.0997x; 1.0532x over previous
#include <cuda_runtime.h>
#include <cuda_bf16.h>
#include <cstdint>

// ---------------- scratch (no cudaMalloc allowed) ----------------
__device__ __nv_bfloat16 g_A2[4096 * 2304];          // x-split, later ao-split [hi|lo|hi]
__device__ __nv_bfloat16 g_B1[2304 * 2304];          // qkv_w split [hi|hi|lo]
__device__ __nv_bfloat16 g_B2[768 * 2304];           // proj_w split [hi|hi|lo]
__device__ __nv_bfloat16 g_Q2[24 * 2048 * 128];      // per-head hi|lo (Q pre-scaled)
__device__ __nv_bfloat16 g_K2[24 * 2048 * 128];
__device__ __nv_bfloat16 g_V2[24 * 2048 * 128];
__device__ float g_Op[2 * 24 * 2048 * 64];           // partial O  [half][bh][row][d]
__device__ float g_Ml[2 * 24 * 2048 * 2];            // partial m,l [half][bh][row]

#define QSC 0.18033688f   // 0.125 * log2(e)

// ================= helpers =================
__device__ __forceinline__ uint32_t smem_u32(const void* p) {
    uint32_t a;
    asm("{ .reg .u64 t; cvta.to.shared.u64 t, %1; cvt.u32.u64 %0, t; }" : "=r"(a) : "l"(p));
    return a;
}
__device__ __forceinline__ void ldsm4(uint32_t* r, uint32_t a) {
    asm volatile("ldmatrix.sync.aligned.m8n8.x4.shared.b16 {%0,%1,%2,%3}, [%4];"
                 : "=r"(r[0]), "=r"(r[1]), "=r"(r[2]), "=r"(r[3]) : "r"(a));
}
__device__ __forceinline__ void ldsm4t(uint32_t* r, uint32_t a) {
    asm volatile("ldmatrix.sync.aligned.m8n8.x4.trans.shared.b16 {%0,%1,%2,%3}, [%4];"
                 : "=r"(r[0]), "=r"(r[1]), "=r"(r[2]), "=r"(r[3]) : "r"(a));
}
__device__ __forceinline__ void mma16816(float* d, const uint32_t* a, uint32_t b0, uint32_t b1) {
    asm volatile("mma.sync.aligned.m16n8k16.row.col.f32.bf16.bf16.f32 "
                 "{%0,%1,%2,%3},{%4,%5,%6,%7},{%8,%9},{%0,%1,%2,%3};"
                 : "+f"(d[0]), "+f"(d[1]), "+f"(d[2]), "+f"(d[3])
                 : "r"(a[0]), "r"(a[1]), "r"(a[2]), "r"(a[3]), "r"(b0), "r"(b1));
}
__device__ __forceinline__ void cp16(uint32_t saddr, const void* gaddr) {
    asm volatile("cp.async.cg.shared.global [%0], [%1], 16;" :: "r"(saddr), "l"(gaddr));
}
__device__ __forceinline__ void cp_commit() { asm volatile("cp.async.commit_group;" ::: "memory"); }
__device__ __forceinline__ void cp_wait2()  { asm volatile("cp.async.wait_group 2;" ::: "memory"); }
__device__ __forceinline__ void cp_wait1()  { asm volatile("cp.async.wait_group 1;" ::: "memory"); }
__device__ __forceinline__ void cp_wait0()  { asm volatile("cp.async.wait_group 0;" ::: "memory"); }

__device__ __forceinline__ void split2(float x, float y, __nv_bfloat162& hi, __nv_bfloat162& lo) {
    hi = __float22bfloat162_rn(make_float2(x, y));
    float2 b = __bfloat1622float2(hi);
    lo = __float22bfloat162_rn(make_float2(x - b.x, y - b.y));
}

// ===== split-concat: f32 -> [R][3K] bf16 (GEMM operands) =====
__global__ void split3(const float* __restrict__ in, __nv_bfloat16* __restrict__ out,
                       int R, int K, int loMid) {
    int i = blockIdx.x * blockDim.x + threadIdx.x;
    int per_row = K >> 2;
    if (i >= R * per_row) return;
    int r = i / per_row, f = i % per_row;
    float4 v = *(const float4*)(in + (size_t)r * K + f * 4);
    __nv_bfloat162 H0, H1, L0, L1;
    split2(v.x, v.y, H0, L0);
    split2(v.z, v.w, H1, L1);
    __nv_bfloat16* o = out + (size_t)r * 3 * K + f * 4;
    ((__nv_bfloat162*)o)[0] = H0;  ((__nv_bfloat162*)o)[1] = H1;
    if (loMid) {
        ((__nv_bfloat162*)(o + K))[0] = L0;     ((__nv_bfloat162*)(o + K))[1] = L1;
        ((__nv_bfloat162*)(o + 2 * K))[0] = H0; ((__nv_bfloat162*)(o + 2 * K))[1] = H1;
    } else {
        ((__nv_bfloat162*)(o + K))[0] = H0;     ((__nv_bfloat162*)(o + K))[1] = H1;
        ((__nv_bfloat162*)(o + 2 * K))[0] = L0; ((__nv_bfloat162*)(o + 2 * K))[1] = L1;
    }
}

// ================= bf16 GEMM, 4-stage, templated N-tile =================
// BM=128 fixed; BN in {128, 64}. 8 warps (4m x 2n). Optional fused split output (BN=128).
template<int BN>
__global__ __launch_bounds__(256, 2)
void mma_gemm(const __nv_bfloat16* __restrict__ A, const __nv_bfloat16* __restrict__ B,
              const float* __restrict__ bias, float* __restrict__ C,
              __nv_bfloat16* __restrict__ Q2o, __nv_bfloat16* __restrict__ K2o,
              __nv_bfloat16* __restrict__ V2o, int splitOut,
              int M, int N, int K3) {
    constexpr int WN = BN / 2;      // cols per warp
    constexpr int NP = WN / 16;     // 16-col ldsm groups
    constexpr int NT = WN / 8;      // 8-col mma groups
    constexpr int STAGE = 10240 + BN * 80;

    extern __shared__ char sm[];
    const uint32_t sb = smem_u32(sm);
    const int tid = threadIdx.x, wid = tid >> 5, lane = tid & 31;
    const int wm = wid & 3, wn = wid >> 2;
    const int mBase = blockIdx.y * 128, nBase = blockIdx.x * BN;
    const int NIT = K3 / 32;

    float acc[2][NT][4] = {};

    auto load_stage = [&](int st, int k0) {
        uint32_t sA = sb + st * STAGE, sB2 = sA + 10240;
#pragma unroll
        for (int i2 = 0; i2 < 2; i2++) {
            int c = tid + i2 * 256;
            int row = c >> 2, kc = c & 3;
            cp16(sA + row * 80 + kc * 16, A + (size_t)(mBase + row) * K3 + k0 + kc * 8);
        }
#pragma unroll
        for (int i2 = 0; i2 < BN / 64; i2++) {
            int c = tid + i2 * 256;
            int row = c >> 2, kc = c & 3;
            cp16(sB2 + row * 80 + kc * 16, B + (size_t)(nBase + row) * K3 + k0 + kc * 8);
        }
    };

    load_stage(0, 0);  cp_commit();
    load_stage(1, 32); cp_commit();
    load_stage(2, 64); cp_commit();

    for (int it = 0; it < NIT; it++) {
        cp_wait2();
        __syncthreads();
        if (it + 3 < NIT) { load_stage((it + 3) & 3, (it + 3) * 32); }
        cp_commit();

        uint32_t sA = sb + (it & 3) * STAGE, sB2 = sA + 10240;
#pragma unroll
        for (int kk = 0; kk < 2; kk++) {
            uint32_t a[2][4], bq[NP][4];
#pragma unroll
            for (int mt = 0; mt < 2; mt++)
                ldsm4(a[mt], sA + (wm * 32 + mt * 16 + (lane & 15)) * 80 + kk * 32 + (lane >> 4) * 16);
#pragma unroll
            for (int p = 0; p < NP; p++)
                ldsm4(bq[p], sB2 + (wn * WN + p * 16 + (lane & 15)) * 80 + kk * 32 + (lane >> 4) * 16);
#pragma unroll
            for (int mt = 0; mt < 2; mt++)
#pragma unroll
                for (int nt = 0; nt < NT; nt++) {
                    int p = nt >> 1, j = nt & 1;
                    mma16816(acc[mt][nt], a[mt], bq[p][j], bq[p][j + 2]);
                }
        }
    }

    const int cbase = nBase + wn * WN;
#pragma unroll
    for (int nt = 0; nt < NT; nt++) {
        int col = cbase + nt * 8 + 2 * (lane & 3);
        float2 bv = *(const float2*)(bias + col);
#pragma unroll
        for (int mt = 0; mt < 2; mt++) {
            int r0 = mBase + wm * 32 + mt * 16 + (lane >> 2);
            float2 v0; v0.x = acc[mt][nt][0] + bv.x; v0.y = acc[mt][nt][1] + bv.y;
            float2 v1; v1.x = acc[mt][nt][2] + bv.x; v1.y = acc[mt][nt][3] + bv.y;
            if (!splitOut) {
                *(float2*)(C + (size_t)r0 * N + col) = v0;
                *(float2*)(C + (size_t)(r0 + 8) * N + col) = v1;
            } else {
                int m = col / 768;
                int hc = col - m * 768;
                int h = hc >> 6, d = hc & 63;
                __nv_bfloat16* base = (m == 0 ? Q2o : m == 1 ? K2o : V2o);
                float qs = (m == 0) ? QSC : 1.0f;
                __nv_bfloat162 H, L;
#pragma unroll
                for (int rr = 0; rr < 2; rr++) {
                    int r = r0 + rr * 8;
                    float2 v = rr ? v1 : v0;
                    split2(v.x * qs, v.y * qs, H, L);
                    __nv_bfloat16* dst = base +
                        ((size_t)((r >> 11) * 12 + h) * 2048 + (r & 2047)) * 128 + d;
                    *(__nv_bfloat162*)dst = H;
                    *(__nv_bfloat162*)(dst + 64) = L;
                }
            }
        }
    }
}

// ================= flash attention v9: 4-stage ring, 1 sync/iter =================
// Grid (16, 24, 2); kv half per CTA (32 iters). 2 CTAs/SM.
// Smem: Q 128x272 = 34816 ; 4 stages x (K 32x272 + V 64x144) = 4 x 17920 = 71680. Total 106496.
#define AT9_SMEM (34816 + 4 * 17920)

__device__ __forceinline__ void computeS(float (&sc)[4][4], uint32_t Qu, uint32_t Kst,
                                         int wid, int lane) {
#pragma unroll
    for (int nt = 0; nt < 4; nt++)
#pragma unroll
        for (int j = 0; j < 4; j++) sc[nt][j] = 0.f;
#pragma unroll
    for (int g = 0; g < 4; g++) {
        const uint32_t qrow = Qu + (wid * 16 + (lane & 15)) * 272 + g * 32 + (lane >> 4) * 16;
        const uint32_t krow0 = Kst + (lane & 15) * 272 + g * 32 + (lane >> 4) * 16;
        const uint32_t krow1 = Kst + (16 + (lane & 15)) * 272 + g * 32 + (lane >> 4) * 16;
        uint32_t aqh[4], aql[4], bh0[4], bh1[4], bl0[4], bl1[4];
        ldsm4(aqh, qrow);
        ldsm4(aql, qrow + 128);
        ldsm4(bh0, krow0);
        ldsm4(bh1, krow1);
        ldsm4(bl0, krow0 + 128);
        ldsm4(bl1, krow1 + 128);
        mma16816(sc[0], aqh, bh0[0], bh0[2]); mma16816(sc[1], aqh, bh0[1], bh0[3]);
        mma16816(sc[2], aqh, bh1[0], bh1[2]); mma16816(sc[3], aqh, bh1[1], bh1[3]);
        mma16816(sc[0], aql, bh0[0], bh0[2]); mma16816(sc[1], aql, bh0[1], bh0[3]);
        mma16816(sc[2], aql, bh1[0], bh1[2]); mma16816(sc[3], aql, bh1[1], bh1[3]);
        mma16816(sc[0], aqh, bl0[0], bl0[2]); mma16816(sc[1], aqh, bl0[1], bl0[3]);
        mma16816(sc[2], aqh, bl1[0], bl1[2]); mma16816(sc[3], aqh, bl1[1], bl1[3]);
    }
}

__global__ __launch_bounds__(256, 2)
void attn9(const __nv_bfloat16* __restrict__ Q2, const __nv_bfloat16* __restrict__ K2,
           const __nv_bfloat16* __restrict__ V2, float* __restrict__ Op,
           float* __restrict__ Ml) {
    extern __shared__ char sm[];
    const uint32_t sb = smem_u32(sm);
    const uint32_t Qu = sb;

    const int tid = threadIdx.x, wid = tid >> 5, lane = tid & 31;
    const int bh = blockIdx.y;
    const int q0 = blockIdx.x * 128;
    const int half = blockIdx.z;

    const __nv_bfloat16* Qg = Q2 + ((size_t)bh * 2048 + q0) * 128;
    const __nv_bfloat16* Kg0 = K2 + ((size_t)bh * 2048 + half * 1024) * 128;
    const __nv_bfloat16* Vg0 = V2 + ((size_t)bh * 2048 + half * 1024) * 128;

    auto stageK = [&](int st) { return sb + 34816 + st * 17920; };

    auto loadKV = [&](int st, int kt) {
        const __nv_bfloat16* Kg = Kg0 + (size_t)kt * 32 * 128;
        const __nv_bfloat16* Vg = Vg0 + (size_t)kt * 32 * 128;
        uint32_t Ku = stageK(st), Vu = Ku + 8704;
#pragma unroll
        for (int i = 0; i < 2; i++) {
            int idx = tid + i * 256;
            int row = idx >> 4, j = idx & 15;
            cp16(Ku + row * 272 + j * 16, Kg + row * 128 + j * 8);
        }
#pragma unroll
        for (int i = 0; i < 2; i++) {
            int idx = tid + i * 256;
            int row = idx >> 3, j = idx & 7;
            cp16(Vu + row * 144 + j * 16,
                 Vg + (row & 31) * 128 + (row >> 5) * 64 + j * 8);
        }
    };

#pragma unroll
    for (int i = 0; i < 8; i++) {
        int idx = tid + i * 256;
        int row = idx >> 4, j = idx & 15;
        cp16(Qu + row * 272 + j * 16, Qg + row * 128 + j * 8);
    }
    loadKV(0, 0);
    cp_commit();
    loadKV(1, 1);
    cp_commit();
    cp_wait1();
    __syncthreads();

    float oc[8][4] = {};
    float mrow[2] = { -1e30f, -1e30f };
    float lrow[2] = { 0.f, 0.f };       // per-thread partial (deferred quad reduce)
    float sc0[4][4], sc1[4][4];

    computeS(sc0, Qu, stageK(0), wid, lane);

    auto body = [&](float (&scCur)[4][4], float (&scNxt)[4][4], int kt) {
        if (kt + 2 < 32) {
            loadKV((kt + 2) & 3, kt + 2);
            cp_commit();
            cp_wait1();
        } else {
            cp_wait0();
        }
        __syncthreads();   // single barrier: orders KV(kt+1) visibility AND prior PV reads

        if (kt + 1 < 32)
            computeS(scNxt, Qu, stageK((kt + 1) & 3), wid, lane);

        // ---- softmax(kt) (base-2 domain; Q pre-scaled) ----
        float m0 = -1e30f, m1 = -1e30f;
#pragma unroll
        for (int nt = 0; nt < 4; nt++) {
            m0 = fmaxf(m0, fmaxf(scCur[nt][0], scCur[nt][1]));
            m1 = fmaxf(m1, fmaxf(scCur[nt][2], scCur[nt][3]));
        }
        m0 = fmaxf(m0, __shfl_xor_sync(0xffffffffu, m0, 1));
        m0 = fmaxf(m0, __shfl_xor_sync(0xffffffffu, m0, 2));
        m1 = fmaxf(m1, __shfl_xor_sync(0xffffffffu, m1, 1));
        m1 = fmaxf(m1, __shfl_xor_sync(0xffffffffu, m1, 2));
        float mn0 = fmaxf(mrow[0], m0), mn1 = fmaxf(mrow[1], m1);
        float al0 = exp2f(mrow[0] - mn0), al1 = exp2f(mrow[1] - mn1);
        mrow[0] = mn0; mrow[1] = mn1;

        float s0 = 0.f, s1 = 0.f;
#pragma unroll
        for (int nt = 0; nt < 4; nt++) {
            scCur[nt][0] = exp2f(scCur[nt][0] - mn0);
            scCur[nt][1] = exp2f(scCur[nt][1] - mn0);
            scCur[nt][2] = exp2f(scCur[nt][2] - mn1);
            scCur[nt][3] = exp2f(scCur[nt][3] - mn1);
            s0 += scCur[nt][0] + scCur[nt][1];
            s1 += scCur[nt][2] + scCur[nt][3];
        }
        lrow[0] = lrow[0] * al0 + s0;   // partial; quad-reduce at end
        lrow[1] = lrow[1] * al1 + s1;

        // skip O rescale when no row max changed anywhere in warp
        bool resc = !__all_sync(0xffffffffu, (al0 == 1.f) && (al1 == 1.f));
        if (resc) {
#pragma unroll
            for (int nt = 0; nt < 8; nt++) {
                oc[nt][0] *= al0; oc[nt][1] *= al0;
                oc[nt][2] *= al1; oc[nt][3] *= al1;
            }
        }

        const uint32_t Vst = stageK(kt & 3) + 8704;
#pragma unroll
        for (int kg = 0; kg < 2; kg++) {
            uint32_t Ph[4], Pl[4];
#pragma unroll
            for (int e = 0; e < 2; e++) {
                const float* f0 = scCur[kg * 2];
                const float* f1 = scCur[kg * 2 + 1];
                __nv_bfloat162 H, L;
                split2(f0[e * 2], f0[e * 2 + 1], H, L);
                Ph[e] = *(uint32_t*)&H; Pl[e] = *(uint32_t*)&L;
                split2(f1[e * 2], f1[e * 2 + 1], H, L);
                Ph[e + 2] = *(uint32_t*)&H; Pl[e + 2] = *(uint32_t*)&L;
            }
#pragma unroll
            for (int vt = 0; vt < 2; vt++) {
                uint32_t bv[4][4];
#pragma unroll
                for (int p = 0; p < 4; p++)
                    ldsm4t(bv[p], Vst + (vt * 32 + kg * 16 + (lane & 15)) * 144 +
                                   p * 32 + (lane >> 4) * 16);
#pragma unroll
                for (int p = 0; p < 4; p++)
#pragma unroll
                    for (int j = 0; j < 2; j++) {
                        mma16816(oc[p * 2 + j], Ph, bv[p][j * 2], bv[p][j * 2 + 1]);
                        if (vt == 0)
                            mma16816(oc[p * 2 + j], Pl, bv[p][j * 2], bv[p][j * 2 + 1]);
                    }
            }
        }
    };

    for (int kt = 0; kt < 32; kt += 2) {
        body(sc0, sc1, kt);
        body(sc1, sc0, kt + 1);
    }

    // final quad reduce of l
    lrow[0] += __shfl_xor_sync(0xffffffffu, lrow[0], 1);
    lrow[0] += __shfl_xor_sync(0xffffffffu, lrow[0], 2);
    lrow[1] += __shfl_xor_sync(0xffffffffu, lrow[1], 1);
    lrow[1] += __shfl_xor_sync(0xffffffffu, lrow[1], 2);

    // ---- epilogue: partial fp32 O, m, l ----
    {
        int r = q0 + wid * 16 + (lane >> 2);
        size_t rbase = ((size_t)(half * 24 + bh) * 2048 + r);
        float* op0 = Op + rbase * 64;
        float* op1 = Op + (rbase + 8) * 64;
#pragma unroll
        for (int nt = 0; nt < 8; nt++) {
            int c = nt * 8 + 2 * (lane & 3);
            *(float2*)(op0 + c) = make_float2(oc[nt][0], oc[nt][1]);
            *(float2*)(op1 + c) = make_float2(oc[nt][2], oc[nt][3]);
        }
        if ((lane & 3) == 0) {
            *(float2*)(Ml + rbase * 2) = make_float2(mrow[0], lrow[0]);
            *(float2*)(Ml + (rbase + 8) * 2) = make_float2(mrow[1], lrow[1]);
        }
    }
}

// ===== merge halves -> A2 [hi|lo|hi] =====
__global__ void mergeO(const float* __restrict__ Op, const float* __restrict__ Ml,
                       __nv_bfloat16* __restrict__ A2) {
    int i = blockIdx.x * blockDim.x + threadIdx.x;
    if (i >= 24 * 2048 * 8) return;
    int cg = i & 7;
    int row = (i >> 3) & 2047;
    int bh = i >> 14;
    int b = bh / 12, h = bh % 12;

    size_t r1 = (size_t)bh * 2048 + row;
    size_t r2 = (size_t)(24 + bh) * 2048 + row;
    float2 ml1 = *(const float2*)(Ml + r1 * 2);
    float2 ml2 = *(const float2*)(Ml + r2 * 2);
    float mm = fmaxf(ml1.x, ml2.x);
    float a1 = exp2f(ml1.x - mm), a2 = exp2f(ml2.x - mm);
    float inv = 1.0f / (ml1.y * a1 + ml2.y * a2);
    a1 *= inv; a2 *= inv;

    const float* o1 = Op + r1 * 64 + cg * 8;
    const float* o2 = Op + r2 * 64 + cg * 8;
    float4 p1a = *(const float4*)o1, p1b = *(const float4*)(o1 + 4);
    float4 p2a = *(const float4*)o2, p2b = *(const float4*)(o2 + 4);

    float v[8];
    v[0] = p1a.x * a1 + p2a.x * a2; v[1] = p1a.y * a1 + p2a.y * a2;
    v[2] = p1a.z * a1 + p2a.z * a2; v[3] = p1a.w * a1 + p2a.w * a2;
    v[4] = p1b.x * a1 + p2b.x * a2; v[5] = p1b.y * a1 + p2b.y * a2;
    v[6] = p1b.z * a1 + p2b.z * a2; v[7] = p1b.w * a1 + p2b.w * a2;

    __nv_bfloat16* base = A2 + (size_t)(b * 2048 + row) * 2304 + h * 64 + cg * 8;
#pragma unroll
    for (int j = 0; j < 8; j += 2) {
        __nv_bfloat162 H, L;
        split2(v[j], v[j + 1], H, L);
        *(__nv_bfloat162*)(base + j) = H;
        *(__nv_bfloat162*)(base + 768 + j) = L;
        *(__nv_bfloat162*)(base + 1536 + j) = H;
    }
}

// ---------------- launch ----------------
extern "C" void kernel_launch(void* const* d_in, const int* in_sizes, int n_in,
                              void* d_out, int out_size) {
    const float* x      = (const float*)d_in[0];
    const float* qkv_w  = (const float*)d_in[1];
    const float* qkv_b  = (const float*)d_in[2];
    const float* proj_w = (const float*)d_in[3];
    const float* proj_b = (const float*)d_in[4];
    float* out = (float*)d_out;

    __nv_bfloat16 *A2, *B1, *B2, *Q2, *K2, *V2;
    float *Op, *Ml;
    cudaGetSymbolAddress((void**)&A2,  g_A2);
    cudaGetSymbolAddress((void**)&B1,  g_B1);
    cudaGetSymbolAddress((void**)&B2,  g_B2);
    cudaGetSymbolAddress((void**)&Q2,  g_Q2);
    cudaGetSymbolAddress((void**)&K2,  g_K2);
    cudaGetSymbolAddress((void**)&V2,  g_V2);
    cudaGetSymbolAddress((void**)&Op,  g_Op);
    cudaGetSymbolAddress((void**)&Ml,  g_Ml);

    const int gemm_smem_128 = 4 * (10240 + 128 * 80);  // 81920
    const int gemm_smem_64  = 4 * (10240 + 64 * 80);   // 61440
    cudaFuncSetAttribute(mma_gemm<128>, cudaFuncAttributeMaxDynamicSharedMemorySize, gemm_smem_128);
    cudaFuncSetAttribute(mma_gemm<64>,  cudaFuncAttributeMaxDynamicSharedMemorySize, gemm_smem_64);
    cudaFuncSetAttribute(attn9, cudaFuncAttributeMaxDynamicSharedMemorySize, AT9_SMEM);

    split3<<<(4096 * 192 + 255) / 256, 256>>>(x, A2, 4096, 768, 1);
    split3<<<(2304 * 192 + 255) / 256, 256>>>(qkv_w, B1, 2304, 768, 0);

    // 1) qkv GEMM with fused per-head hi/lo split output (Q pre-scaled by QSC)
    mma_gemm<128><<<dim3(18, 32), 256, gemm_smem_128>>>(A2, B1, qkv_b, nullptr,
                                                        Q2, K2, V2, 1, 4096, 2304, 2304);

    // 2) attention: kv-split halves -> partial (O,m,l), merge -> A2
    attn9<<<dim3(16, 24, 2), 256, AT9_SMEM>>>(Q2, K2, V2, Op, Ml);
    mergeO<<<(24 * 2048 * 8 + 255) / 256, 256>>>(Op, Ml, A2);

    split3<<<(768 * 192 + 255) / 256, 256>>>(proj_w, B2, 768, 768, 0);

    // 3) out = ao @ proj_w^T + proj_b (BN=64 tiles: 384 CTAs, 1.3 waves)
    mma_gemm<64><<<dim3(12, 32), 256, gemm_smem_64>>>(A2, B2, proj_b, out,
                                                      nullptr, nullptr, nullptr, 0, 4096, 768, 2304);
}

// round 14
// speedup vs baseline: 1.4171x; 1.2886x over previous
#include <cuda_runtime.h>
#include <cuda_bf16.h>
#include <cstdint>

// ---------------- scratch (no cudaMalloc allowed) ----------------
__device__ float g_Xr [4096 * 768];                  // x, tf32-rounded
__device__ float g_W1r[2304 * 768];                  // qkv_w, tf32-rounded
__device__ float g_W2r[768 * 768];                   // proj_w, tf32-rounded
__device__ float g_AOr[4096 * 768];                  // attention out, tf32-rounded
__device__ __nv_bfloat16 g_Q2[24 * 2048 * 128];      // per-head hi|lo (Q pre-scaled)
__device__ __nv_bfloat16 g_K2[24 * 2048 * 128];
__device__ __nv_bfloat16 g_V2[24 * 2048 * 128];
__device__ float g_Op[2 * 24 * 2048 * 64];           // partial O  [half][bh][row][d]
__device__ float g_Ml[2 * 24 * 2048 * 2];            // partial m,l [half][bh][row]

#define QSC 0.18033688f   // 0.125 * log2(e)

// ================= helpers =================
__device__ __forceinline__ uint32_t smem_u32(const void* p) {
    uint32_t a;
    asm("{ .reg .u64 t; cvta.to.shared.u64 t, %1; cvt.u32.u64 %0, t; }" : "=r"(a) : "l"(p));
    return a;
}
__device__ __forceinline__ void ldsm4(uint32_t* r, uint32_t a) {
    asm volatile("ldmatrix.sync.aligned.m8n8.x4.shared.b16 {%0,%1,%2,%3}, [%4];"
                 : "=r"(r[0]), "=r"(r[1]), "=r"(r[2]), "=r"(r[3]) : "r"(a));
}
__device__ __forceinline__ void ldsm4t(uint32_t* r, uint32_t a) {
    asm volatile("ldmatrix.sync.aligned.m8n8.x4.trans.shared.b16 {%0,%1,%2,%3}, [%4];"
                 : "=r"(r[0]), "=r"(r[1]), "=r"(r[2]), "=r"(r[3]) : "r"(a));
}
__device__ __forceinline__ void mma16816(float* d, const uint32_t* a, uint32_t b0, uint32_t b1) {
    asm volatile("mma.sync.aligned.m16n8k16.row.col.f32.bf16.bf16.f32 "
                 "{%0,%1,%2,%3},{%4,%5,%6,%7},{%8,%9},{%0,%1,%2,%3};"
                 : "+f"(d[0]), "+f"(d[1]), "+f"(d[2]), "+f"(d[3])
                 : "r"(a[0]), "r"(a[1]), "r"(a[2]), "r"(a[3]), "r"(b0), "r"(b1));
}
__device__ __forceinline__ void mma_tf32(float* d, const uint32_t* a, uint32_t b0, uint32_t b1) {
    asm volatile("mma.sync.aligned.m16n8k8.row.col.f32.tf32.tf32.f32 "
                 "{%0,%1,%2,%3},{%4,%5,%6,%7},{%8,%9},{%0,%1,%2,%3};"
                 : "+f"(d[0]), "+f"(d[1]), "+f"(d[2]), "+f"(d[3])
                 : "r"(a[0]), "r"(a[1]), "r"(a[2]), "r"(a[3]), "r"(b0), "r"(b1));
}
__device__ __forceinline__ void cp16(uint32_t saddr, const void* gaddr) {
    asm volatile("cp.async.cg.shared.global [%0], [%1], 16;" :: "r"(saddr), "l"(gaddr));
}
__device__ __forceinline__ void cp_commit() { asm volatile("cp.async.commit_group;" ::: "memory"); }
__device__ __forceinline__ void cp_wait1()  { asm volatile("cp.async.wait_group 1;" ::: "memory"); }
__device__ __forceinline__ void cp_wait0()  { asm volatile("cp.async.wait_group 0;" ::: "memory"); }

__device__ __forceinline__ float tf32r(float x) {
    uint32_t r;
    asm("cvt.rna.tf32.f32 %0, %1;" : "=r"(r) : "f"(x));
    return __uint_as_float(r);
}
__device__ __forceinline__ void split2(float x, float y, __nv_bfloat162& hi, __nv_bfloat162& lo) {
    hi = __float22bfloat162_rn(make_float2(x, y));
    float2 b = __bfloat1622float2(hi);
    lo = __float22bfloat162_rn(make_float2(x - b.x, y - b.y));
}

// ===== elementwise tf32 rounding (rna) =====
__global__ void rnd32(const float* __restrict__ in, float* __restrict__ out, int n4) {
    int i = blockIdx.x * blockDim.x + threadIdx.x;
    if (i >= n4) return;
    float4 v = ((const float4*)in)[i];
    v.x = tf32r(v.x); v.y = tf32r(v.y); v.z = tf32r(v.z); v.w = tf32r(v.w);
    ((float4*)out)[i] = v;
}

// ================= TF32 GEMM: C[M,N] = A[M,K] @ B[N,K]^T + bias =================
// BM=128, BN in {128,64}, BK=32 fp32. 8 warps (4m x 2n). 3-stage cp.async.
// Smem rows: 32 fp32 = 128B, 16B chunks XOR-swizzled by (row&7).
template<int BN>
__global__ __launch_bounds__(256, 2)
void tf32_gemm(const float* __restrict__ A, const float* __restrict__ B,
               const float* __restrict__ bias, float* __restrict__ C,
               __nv_bfloat16* __restrict__ Q2o, __nv_bfloat16* __restrict__ K2o,
               __nv_bfloat16* __restrict__ V2o, int splitOut,
               int M, int N, int K) {
    constexpr int WN = BN / 2;          // cols per warp
    constexpr int NT = WN / 8;          // 8-col mma tiles per warp
    constexpr int ASTG = 128 * 128;     // A stage bytes
    constexpr int BSTG = BN * 128;      // B stage bytes
    constexpr int STAGE = ASTG + BSTG;

    extern __shared__ char sm[];
    const uint32_t sb = smem_u32(sm);
    const int tid = threadIdx.x, wid = tid >> 5, lane = tid & 31;
    const int wm = wid & 3, wn = wid >> 2;
    const int mBase = blockIdx.y * 128, nBase = blockIdx.x * BN;
    const int NIT = K / 32;

    float acc[2][NT][4] = {};

    auto load_stage = [&](int st, int k0) {
        uint32_t sA = sb + st * STAGE, sB2 = sA + ASTG;
#pragma unroll
        for (int i2 = 0; i2 < 4; i2++) {                  // A: 128 rows x 8 chunks
            int c = tid + i2 * 256;
            int row = c >> 3, j = c & 7;
            cp16(sA + row * 128 + ((j ^ (row & 7)) << 4),
                 A + (size_t)(mBase + row) * K + k0 + j * 4);
        }
#pragma unroll
        for (int i2 = 0; i2 < BN / 32; i2++) {            // B: BN rows x 8 chunks
            int c = tid + i2 * 256;
            int row = c >> 3, j = c & 7;
            cp16(sB2 + row * 128 + ((j ^ (row & 7)) << 4),
                 B + (size_t)(nBase + row) * K + k0 + j * 4);
        }
    };

    load_stage(0, 0);  cp_commit();
    load_stage(1, 32); cp_commit();

    for (int it = 0; it < NIT; it++) {
        if (it + 2 < NIT) cp_wait1(); else cp_wait0();
        __syncthreads();
        if (it + 2 < NIT) { load_stage((it + 2) % 3, (it + 2) * 32); cp_commit(); }

        uint32_t sA = sb + (it % 3) * STAGE, sB2 = sA + ASTG;
#pragma unroll
        for (int s = 0; s < 4; s++) {               // 4 k8 steps
            uint32_t a[2][4], bq[NT / 2][4];
            int tA = lane >> 3;                      // tile index 0..3
#pragma unroll
            for (int mt = 0; mt < 2; mt++) {
                int row = wm * 32 + mt * 16 + (tA & 1) * 8 + (lane & 7);
                int chunk = s * 2 + (tA >> 1);
                ldsm4(a[mt], sA + row * 128 + ((chunk ^ (row & 7)) << 4));
            }
#pragma unroll
            for (int p2 = 0; p2 < NT / 2; p2++) {    // each x4 covers 2 n-tiles
                int row = nBase ? 0 : 0;             // (no-op; keep compiler calm)
                int nrow = wn * WN + p2 * 16 + (tA >> 1) * 8 + (lane & 7);
                int chunk = s * 2 + (tA & 1);
                ldsm4(bq[p2], sB2 + nrow * 128 + ((chunk ^ (nrow & 7)) << 4));
            }
#pragma unroll
            for (int mt = 0; mt < 2; mt++)
#pragma unroll
                for (int nt = 0; nt < NT; nt++) {
                    int p2 = nt >> 1, j = nt & 1;
                    mma_tf32(acc[mt][nt], a[mt], bq[p2][j * 2], bq[p2][j * 2 + 1]);
                }
        }
    }

    const int cbase = nBase + wn * WN;
#pragma unroll
    for (int nt = 0; nt < NT; nt++) {
        int col = cbase + nt * 8 + 2 * (lane & 3);
        float2 bv = *(const float2*)(bias + col);
#pragma unroll
        for (int mt = 0; mt < 2; mt++) {
            int r0 = mBase + wm * 32 + mt * 16 + (lane >> 2);
            float2 v0; v0.x = acc[mt][nt][0] + bv.x; v0.y = acc[mt][nt][1] + bv.y;
            float2 v1; v1.x = acc[mt][nt][2] + bv.x; v1.y = acc[mt][nt][3] + bv.y;
            if (!splitOut) {
                *(float2*)(C + (size_t)r0 * N + col) = v0;
                *(float2*)(C + (size_t)(r0 + 8) * N + col) = v1;
            } else {
                int m = col / 768;
                int hc = col - m * 768;
                int h = hc >> 6, d = hc & 63;
                __nv_bfloat16* base = (m == 0 ? Q2o : m == 1 ? K2o : V2o);
                float qs = (m == 0) ? QSC : 1.0f;
                __nv_bfloat162 H, L;
#pragma unroll
                for (int rr = 0; rr < 2; rr++) {
                    int r = r0 + rr * 8;
                    float2 v = rr ? v1 : v0;
                    split2(v.x * qs, v.y * qs, H, L);
                    __nv_bfloat16* dst = base +
                        ((size_t)((r >> 11) * 12 + h) * 2048 + (r & 2047)) * 128 + d;
                    *(__nv_bfloat162*)dst = H;
                    *(__nv_bfloat162*)(dst + 64) = L;
                }
            }
        }
    }
}

// ================= flash attention v9 (validated R13) =================
#define AT9_SMEM (34816 + 4 * 17920)

__device__ __forceinline__ void computeS(float (&sc)[4][4], uint32_t Qu, uint32_t Kst,
                                         int wid, int lane) {
#pragma unroll
    for (int nt = 0; nt < 4; nt++)
#pragma unroll
        for (int j = 0; j < 4; j++) sc[nt][j] = 0.f;
#pragma unroll
    for (int g = 0; g < 4; g++) {
        const uint32_t qrow = Qu + (wid * 16 + (lane & 15)) * 272 + g * 32 + (lane >> 4) * 16;
        const uint32_t krow0 = Kst + (lane & 15) * 272 + g * 32 + (lane >> 4) * 16;
        const uint32_t krow1 = Kst + (16 + (lane & 15)) * 272 + g * 32 + (lane >> 4) * 16;
        uint32_t aqh[4], aql[4], bh0[4], bh1[4], bl0[4], bl1[4];
        ldsm4(aqh, qrow);
        ldsm4(aql, qrow + 128);
        ldsm4(bh0, krow0);
        ldsm4(bh1, krow1);
        ldsm4(bl0, krow0 + 128);
        ldsm4(bl1, krow1 + 128);
        mma16816(sc[0], aqh, bh0[0], bh0[2]); mma16816(sc[1], aqh, bh0[1], bh0[3]);
        mma16816(sc[2], aqh, bh1[0], bh1[2]); mma16816(sc[3], aqh, bh1[1], bh1[3]);
        mma16816(sc[0], aql, bh0[0], bh0[2]); mma16816(sc[1], aql, bh0[1], bh0[3]);
        mma16816(sc[2], aql, bh1[0], bh1[2]); mma16816(sc[3], aql, bh1[1], bh1[3]);
        mma16816(sc[0], aqh, bl0[0], bl0[2]); mma16816(sc[1], aqh, bl0[1], bl0[3]);
        mma16816(sc[2], aqh, bl1[0], bl1[2]); mma16816(sc[3], aqh, bl1[1], bl1[3]);
    }
}

__global__ __launch_bounds__(256, 2)
void attn9(const __nv_bfloat16* __restrict__ Q2, const __nv_bfloat16* __restrict__ K2,
           const __nv_bfloat16* __restrict__ V2, float* __restrict__ Op,
           float* __restrict__ Ml) {
    extern __shared__ char sm[];
    const uint32_t sb = smem_u32(sm);
    const uint32_t Qu = sb;

    const int tid = threadIdx.x, wid = tid >> 5, lane = tid & 31;
    const int bh = blockIdx.y;
    const int q0 = blockIdx.x * 128;
    const int half = blockIdx.z;

    const __nv_bfloat16* Qg = Q2 + ((size_t)bh * 2048 + q0) * 128;
    const __nv_bfloat16* Kg0 = K2 + ((size_t)bh * 2048 + half * 1024) * 128;
    const __nv_bfloat16* Vg0 = V2 + ((size_t)bh * 2048 + half * 1024) * 128;

    auto stageK = [&](int st) { return sb + 34816 + st * 17920; };

    auto loadKV = [&](int st, int kt) {
        const __nv_bfloat16* Kg = Kg0 + (size_t)kt * 32 * 128;
        const __nv_bfloat16* Vg = Vg0 + (size_t)kt * 32 * 128;
        uint32_t Ku = stageK(st), Vu = Ku + 8704;
#pragma unroll
        for (int i = 0; i < 2; i++) {
            int idx = tid + i * 256;
            int row = idx >> 4, j = idx & 15;
            cp16(Ku + row * 272 + j * 16, Kg + row * 128 + j * 8);
        }
#pragma unroll
        for (int i = 0; i < 2; i++) {
            int idx = tid + i * 256;
            int row = idx >> 3, j = idx & 7;
            cp16(Vu + row * 144 + j * 16,
                 Vg + (row & 31) * 128 + (row >> 5) * 64 + j * 8);
        }
    };

#pragma unroll
    for (int i = 0; i < 8; i++) {
        int idx = tid + i * 256;
        int row = idx >> 4, j = idx & 15;
        cp16(Qu + row * 272 + j * 16, Qg + row * 128 + j * 8);
    }
    loadKV(0, 0);
    cp_commit();
    loadKV(1, 1);
    cp_commit();
    cp_wait1();
    __syncthreads();

    float oc[8][4] = {};
    float mrow[2] = { -1e30f, -1e30f };
    float lrow[2] = { 0.f, 0.f };
    float sc0[4][4], sc1[4][4];

    computeS(sc0, Qu, stageK(0), wid, lane);

    auto body = [&](float (&scCur)[4][4], float (&scNxt)[4][4], int kt) {
        if (kt + 2 < 32) {
            loadKV((kt + 2) & 3, kt + 2);
            cp_commit();
            cp_wait1();
        } else {
            cp_wait0();
        }
        __syncthreads();

        if (kt + 1 < 32)
            computeS(scNxt, Qu, stageK((kt + 1) & 3), wid, lane);

        float m0 = -1e30f, m1 = -1e30f;
#pragma unroll
        for (int nt = 0; nt < 4; nt++) {
            m0 = fmaxf(m0, fmaxf(scCur[nt][0], scCur[nt][1]));
            m1 = fmaxf(m1, fmaxf(scCur[nt][2], scCur[nt][3]));
        }
        m0 = fmaxf(m0, __shfl_xor_sync(0xffffffffu, m0, 1));
        m0 = fmaxf(m0, __shfl_xor_sync(0xffffffffu, m0, 2));
        m1 = fmaxf(m1, __shfl_xor_sync(0xffffffffu, m1, 1));
        m1 = fmaxf(m1, __shfl_xor_sync(0xffffffffu, m1, 2));
        float mn0 = fmaxf(mrow[0], m0), mn1 = fmaxf(mrow[1], m1);
        float al0 = exp2f(mrow[0] - mn0), al1 = exp2f(mrow[1] - mn1);
        mrow[0] = mn0; mrow[1] = mn1;

        float s0 = 0.f, s1 = 0.f;
#pragma unroll
        for (int nt = 0; nt < 4; nt++) {
            scCur[nt][0] = exp2f(scCur[nt][0] - mn0);
            scCur[nt][1] = exp2f(scCur[nt][1] - mn0);
            scCur[nt][2] = exp2f(scCur[nt][2] - mn1);
            scCur[nt][3] = exp2f(scCur[nt][3] - mn1);
            s0 += scCur[nt][0] + scCur[nt][1];
            s1 += scCur[nt][2] + scCur[nt][3];
        }
        lrow[0] = lrow[0] * al0 + s0;
        lrow[1] = lrow[1] * al1 + s1;

        bool resc = !__all_sync(0xffffffffu, (al0 == 1.f) && (al1 == 1.f));
        if (resc) {
#pragma unroll
            for (int nt = 0; nt < 8; nt++) {
                oc[nt][0] *= al0; oc[nt][1] *= al0;
                oc[nt][2] *= al1; oc[nt][3] *= al1;
            }
        }

        const uint32_t Vst = stageK(kt & 3) + 8704;
#pragma unroll
        for (int kg = 0; kg < 2; kg++) {
            uint32_t Ph[4], Pl[4];
#pragma unroll
            for (int e = 0; e < 2; e++) {
                const float* f0 = scCur[kg * 2];
                const float* f1 = scCur[kg * 2 + 1];
                __nv_bfloat162 H, L;
                split2(f0[e * 2], f0[e * 2 + 1], H, L);
                Ph[e] = *(uint32_t*)&H; Pl[e] = *(uint32_t*)&L;
                split2(f1[e * 2], f1[e * 2 + 1], H, L);
                Ph[e + 2] = *(uint32_t*)&H; Pl[e + 2] = *(uint32_t*)&L;
            }
#pragma unroll
            for (int vt = 0; vt < 2; vt++) {
                uint32_t bv[4][4];
#pragma unroll
                for (int p = 0; p < 4; p++)
                    ldsm4t(bv[p], Vst + (vt * 32 + kg * 16 + (lane & 15)) * 144 +
                                   p * 32 + (lane >> 4) * 16);
#pragma unroll
                for (int p = 0; p < 4; p++)
#pragma unroll
                    for (int j = 0; j < 2; j++) {
                        mma16816(oc[p * 2 + j], Ph, bv[p][j * 2], bv[p][j * 2 + 1]);
                        if (vt == 0)
                            mma16816(oc[p * 2 + j], Pl, bv[p][j * 2], bv[p][j * 2 + 1]);
                    }
            }
        }
    };

    for (int kt = 0; kt < 32; kt += 2) {
        body(sc0, sc1, kt);
        body(sc1, sc0, kt + 1);
    }

    lrow[0] += __shfl_xor_sync(0xffffffffu, lrow[0], 1);
    lrow[0] += __shfl_xor_sync(0xffffffffu, lrow[0], 2);
    lrow[1] += __shfl_xor_sync(0xffffffffu, lrow[1], 1);
    lrow[1] += __shfl_xor_sync(0xffffffffu, lrow[1], 2);

    {
        int r = q0 + wid * 16 + (lane >> 2);
        size_t rbase = ((size_t)(half * 24 + bh) * 2048 + r);
        float* op0 = Op + rbase * 64;
        float* op1 = Op + (rbase + 8) * 64;
#pragma unroll
        for (int nt = 0; nt < 8; nt++) {
            int c = nt * 8 + 2 * (lane & 3);
            *(float2*)(op0 + c) = make_float2(oc[nt][0], oc[nt][1]);
            *(float2*)(op1 + c) = make_float2(oc[nt][2], oc[nt][3]);
        }
        if ((lane & 3) == 0) {
            *(float2*)(Ml + rbase * 2) = make_float2(mrow[0], lrow[0]);
            *(float2*)(Ml + (rbase + 8) * 2) = make_float2(mrow[1], lrow[1]);
        }
    }
}

// ===== merge halves -> AOr fp32 (tf32-rounded, ready as proj A-operand) =====
__global__ void mergeO(const float* __restrict__ Op, const float* __restrict__ Ml,
                       float* __restrict__ AOr) {
    int i = blockIdx.x * blockDim.x + threadIdx.x;
    if (i >= 24 * 2048 * 8) return;
    int cg = i & 7;
    int row = (i >> 3) & 2047;
    int bh = i >> 14;
    int b = bh / 12, h = bh % 12;

    size_t r1 = (size_t)bh * 2048 + row;
    size_t r2 = (size_t)(24 + bh) * 2048 + row;
    float2 ml1 = *(const float2*)(Ml + r1 * 2);
    float2 ml2 = *(const float2*)(Ml + r2 * 2);
    float mm = fmaxf(ml1.x, ml2.x);
    float a1 = exp2f(ml1.x - mm), a2 = exp2f(ml2.x - mm);
    float inv = 1.0f / (ml1.y * a1 + ml2.y * a2);
    a1 *= inv; a2 *= inv;

    const float* o1 = Op + r1 * 64 + cg * 8;
    const float* o2 = Op + r2 * 64 + cg * 8;
    float4 p1a = *(const float4*)o1, p1b = *(const float4*)(o1 + 4);
    float4 p2a = *(const float4*)o2, p2b = *(const float4*)(o2 + 4);

    float4 va, vb;
    va.x = tf32r(p1a.x * a1 + p2a.x * a2); va.y = tf32r(p1a.y * a1 + p2a.y * a2);
    va.z = tf32r(p1a.z * a1 + p2a.z * a2); va.w = tf32r(p1a.w * a1 + p2a.w * a2);
    vb.x = tf32r(p1b.x * a1 + p2b.x * a2); vb.y = tf32r(p1b.y * a1 + p2b.y * a2);
    vb.z = tf32r(p1b.z * a1 + p2b.z * a2); vb.w = tf32r(p1b.w * a1 + p2b.w * a2);

    float* base = AOr + (size_t)(b * 2048 + row) * 768 + h * 64 + cg * 8;
    *(float4*)base = va;
    *(float4*)(base + 4) = vb;
}

// ---------------- launch ----------------
extern "C" void kernel_launch(void* const* d_in, const int* in_sizes, int n_in,
                              void* d_out, int out_size) {
    const float* x      = (const float*)d_in[0];
    const float* qkv_w  = (const float*)d_in[1];
    const float* qkv_b  = (const float*)d_in[2];
    const float* proj_w = (const float*)d_in[3];
    const float* proj_b = (const float*)d_in[4];
    float* out = (float*)d_out;

    float *Xr, *W1r, *W2r, *AOr, *Op, *Ml;
    __nv_bfloat16 *Q2, *K2, *V2;
    cudaGetSymbolAddress((void**)&Xr,  g_Xr);
    cudaGetSymbolAddress((void**)&W1r, g_W1r);
    cudaGetSymbolAddress((void**)&W2r, g_W2r);
    cudaGetSymbolAddress((void**)&AOr, g_AOr);
    cudaGetSymbolAddress((void**)&Q2,  g_Q2);
    cudaGetSymbolAddress((void**)&K2,  g_K2);
    cudaGetSymbolAddress((void**)&V2,  g_V2);
    cudaGetSymbolAddress((void**)&Op,  g_Op);
    cudaGetSymbolAddress((void**)&Ml,  g_Ml);

    const int gemm_smem_128 = 3 * (128 + 128) * 128;   // 98304
    const int gemm_smem_64  = 3 * (128 + 64) * 128;    // 73728
    cudaFuncSetAttribute(tf32_gemm<128>, cudaFuncAttributeMaxDynamicSharedMemorySize, gemm_smem_128);
    cudaFuncSetAttribute(tf32_gemm<64>,  cudaFuncAttributeMaxDynamicSharedMemorySize, gemm_smem_64);
    cudaFuncSetAttribute(attn9, cudaFuncAttributeMaxDynamicSharedMemorySize, AT9_SMEM);

    // tf32-round inputs (replaces split3 preprocessing)
    rnd32<<<(4096 * 192 + 255) / 256, 256>>>(x, Xr, 4096 * 192);
    rnd32<<<(2304 * 192 + 255) / 256, 256>>>(qkv_w, W1r, 2304 * 192);
    rnd32<<<(768 * 192 + 255) / 256, 256>>>(proj_w, W2r, 768 * 192);

    // 1) qkv = x @ qkv_w^T + qkv_b (tf32, K=768), fused per-head hi/lo split out
    tf32_gemm<128><<<dim3(18, 32), 256, gemm_smem_128>>>(Xr, W1r, qkv_b, nullptr,
                                                         Q2, K2, V2, 1, 4096, 2304, 768);

    // 2) attention (split-bf16, unchanged): kv halves -> partial, merge -> AOr
    attn9<<<dim3(16, 24, 2), 256, AT9_SMEM>>>(Q2, K2, V2, Op, Ml);
    mergeO<<<(24 * 2048 * 8 + 255) / 256, 256>>>(Op, Ml, AOr);

    // 3) out = ao @ proj_w^T + proj_b (tf32, K=768)
    tf32_gemm<64><<<dim3(12, 32), 256, gemm_smem_64>>>(AOr, W2r, proj_b, out,
                                                       nullptr, nullptr, nullptr, 0, 4096, 768, 768);
}

// round 15
// speedup vs baseline: 1.4592x; 1.0297x over previous
#include <cuda_runtime.h>
#include <cuda_bf16.h>
#include <cstdint>

// ---------------- scratch (no cudaMalloc allowed) ----------------
__device__ float g_Xr [4096 * 768];                  // x, tf32-rounded
__device__ float g_W1r[2304 * 768];                  // qkv_w, tf32-rounded
__device__ float g_W2r[768 * 768];                   // proj_w, tf32-rounded
__device__ float g_AOr[4096 * 768];                  // attention out, tf32-rounded
__device__ __nv_bfloat16 g_Q2[24 * 2048 * 128];      // per-head hi|lo (Q pre-scaled)
__device__ __nv_bfloat16 g_K2[24 * 2048 * 128];
__device__ __nv_bfloat16 g_V2[24 * 2048 * 128];
__device__ float g_Op[2 * 24 * 2048 * 64];           // partial O  [half][bh][row][d]
__device__ float g_Ll[2 * 24 * 2048];                // partial l   [half][bh][row]

#define QSC 0.18033688f   // 0.125 * log2(e)
#define SMAX 16.0f        // static softmax exponent offset (max |S2| << 16)

// ================= helpers =================
__device__ __forceinline__ uint32_t smem_u32(const void* p) {
    uint32_t a;
    asm("{ .reg .u64 t; cvta.to.shared.u64 t, %1; cvt.u32.u64 %0, t; }" : "=r"(a) : "l"(p));
    return a;
}
__device__ __forceinline__ void ldsm4(uint32_t* r, uint32_t a) {
    asm volatile("ldmatrix.sync.aligned.m8n8.x4.shared.b16 {%0,%1,%2,%3}, [%4];"
                 : "=r"(r[0]), "=r"(r[1]), "=r"(r[2]), "=r"(r[3]) : "r"(a));
}
__device__ __forceinline__ void ldsm4t(uint32_t* r, uint32_t a) {
    asm volatile("ldmatrix.sync.aligned.m8n8.x4.trans.shared.b16 {%0,%1,%2,%3}, [%4];"
                 : "=r"(r[0]), "=r"(r[1]), "=r"(r[2]), "=r"(r[3]) : "r"(a));
}
__device__ __forceinline__ void mma16816(float* d, const uint32_t* a, uint32_t b0, uint32_t b1) {
    asm volatile("mma.sync.aligned.m16n8k16.row.col.f32.bf16.bf16.f32 "
                 "{%0,%1,%2,%3},{%4,%5,%6,%7},{%8,%9},{%0,%1,%2,%3};"
                 : "+f"(d[0]), "+f"(d[1]), "+f"(d[2]), "+f"(d[3])
                 : "r"(a[0]), "r"(a[1]), "r"(a[2]), "r"(a[3]), "r"(b0), "r"(b1));
}
__device__ __forceinline__ void mma_tf32(float* d, const uint32_t* a, uint32_t b0, uint32_t b1) {
    asm volatile("mma.sync.aligned.m16n8k8.row.col.f32.tf32.tf32.f32 "
                 "{%0,%1,%2,%3},{%4,%5,%6,%7},{%8,%9},{%0,%1,%2,%3};"
                 : "+f"(d[0]), "+f"(d[1]), "+f"(d[2]), "+f"(d[3])
                 : "r"(a[0]), "r"(a[1]), "r"(a[2]), "r"(a[3]), "r"(b0), "r"(b1));
}
__device__ __forceinline__ void cp16(uint32_t saddr, const void* gaddr) {
    asm volatile("cp.async.cg.shared.global [%0], [%1], 16;" :: "r"(saddr), "l"(gaddr));
}
__device__ __forceinline__ void cp_commit() { asm volatile("cp.async.commit_group;" ::: "memory"); }
__device__ __forceinline__ void cp_wait1()  { asm volatile("cp.async.wait_group 1;" ::: "memory"); }
__device__ __forceinline__ void cp_wait0()  { asm volatile("cp.async.wait_group 0;" ::: "memory"); }

__device__ __forceinline__ float tf32r(float x) {
    uint32_t r;
    asm("cvt.rna.tf32.f32 %0, %1;" : "=r"(r) : "f"(x));
    return __uint_as_float(r);
}
__device__ __forceinline__ void split2(float x, float y, __nv_bfloat162& hi, __nv_bfloat162& lo) {
    hi = __float22bfloat162_rn(make_float2(x, y));
    float2 b = __bfloat1622float2(hi);
    lo = __float22bfloat162_rn(make_float2(x - b.x, y - b.y));
}

// ===== elementwise tf32 rounding (rna) =====
__global__ void rnd32(const float* __restrict__ in, float* __restrict__ out, int n4) {
    int i = blockIdx.x * blockDim.x + threadIdx.x;
    if (i >= n4) return;
    float4 v = ((const float4*)in)[i];
    v.x = tf32r(v.x); v.y = tf32r(v.y); v.z = tf32r(v.z); v.w = tf32r(v.w);
    ((float4*)out)[i] = v;
}

// ================= TF32 GEMM (validated R14) =================
template<int BN>
__global__ __launch_bounds__(256, 2)
void tf32_gemm(const float* __restrict__ A, const float* __restrict__ B,
               const float* __restrict__ bias, float* __restrict__ C,
               __nv_bfloat16* __restrict__ Q2o, __nv_bfloat16* __restrict__ K2o,
               __nv_bfloat16* __restrict__ V2o, int splitOut,
               int M, int N, int K) {
    constexpr int WN = BN / 2;
    constexpr int NT = WN / 8;
    constexpr int ASTG = 128 * 128;
    constexpr int BSTG = BN * 128;
    constexpr int STAGE = ASTG + BSTG;

    extern __shared__ char sm[];
    const uint32_t sb = smem_u32(sm);
    const int tid = threadIdx.x, wid = tid >> 5, lane = tid & 31;
    const int wm = wid & 3, wn = wid >> 2;
    const int mBase = blockIdx.y * 128, nBase = blockIdx.x * BN;
    const int NIT = K / 32;

    float acc[2][NT][4] = {};

    auto load_stage = [&](int st, int k0) {
        uint32_t sA = sb + st * STAGE, sB2 = sA + ASTG;
#pragma unroll
        for (int i2 = 0; i2 < 4; i2++) {
            int c = tid + i2 * 256;
            int row = c >> 3, j = c & 7;
            cp16(sA + row * 128 + ((j ^ (row & 7)) << 4),
                 A + (size_t)(mBase + row) * K + k0 + j * 4);
        }
#pragma unroll
        for (int i2 = 0; i2 < BN / 32; i2++) {
            int c = tid + i2 * 256;
            int row = c >> 3, j = c & 7;
            cp16(sB2 + row * 128 + ((j ^ (row & 7)) << 4),
                 B + (size_t)(nBase + row) * K + k0 + j * 4);
        }
    };

    load_stage(0, 0);  cp_commit();
    load_stage(1, 32); cp_commit();

    for (int it = 0; it < NIT; it++) {
        if (it + 2 < NIT) cp_wait1(); else cp_wait0();
        __syncthreads();
        if (it + 2 < NIT) { load_stage((it + 2) % 3, (it + 2) * 32); cp_commit(); }

        uint32_t sA = sb + (it % 3) * STAGE, sB2 = sA + ASTG;
#pragma unroll
        for (int s = 0; s < 4; s++) {
            uint32_t a[2][4], bq[NT / 2][4];
            int tA = lane >> 3;
#pragma unroll
            for (int mt = 0; mt < 2; mt++) {
                int row = wm * 32 + mt * 16 + (tA & 1) * 8 + (lane & 7);
                int chunk = s * 2 + (tA >> 1);
                ldsm4(a[mt], sA + row * 128 + ((chunk ^ (row & 7)) << 4));
            }
#pragma unroll
            for (int p2 = 0; p2 < NT / 2; p2++) {
                int nrow = wn * WN + p2 * 16 + (tA >> 1) * 8 + (lane & 7);
                int chunk = s * 2 + (tA & 1);
                ldsm4(bq[p2], sB2 + nrow * 128 + ((chunk ^ (nrow & 7)) << 4));
            }
#pragma unroll
            for (int mt = 0; mt < 2; mt++)
#pragma unroll
                for (int nt = 0; nt < NT; nt++) {
                    int p2 = nt >> 1, j = nt & 1;
                    mma_tf32(acc[mt][nt], a[mt], bq[p2][j * 2], bq[p2][j * 2 + 1]);
                }
        }
    }

    const int cbase = nBase + wn * WN;
#pragma unroll
    for (int nt = 0; nt < NT; nt++) {
        int col = cbase + nt * 8 + 2 * (lane & 3);
        float2 bv = *(const float2*)(bias + col);
#pragma unroll
        for (int mt = 0; mt < 2; mt++) {
            int r0 = mBase + wm * 32 + mt * 16 + (lane >> 2);
            float2 v0; v0.x = acc[mt][nt][0] + bv.x; v0.y = acc[mt][nt][1] + bv.y;
            float2 v1; v1.x = acc[mt][nt][2] + bv.x; v1.y = acc[mt][nt][3] + bv.y;
            if (!splitOut) {
                *(float2*)(C + (size_t)r0 * N + col) = v0;
                *(float2*)(C + (size_t)(r0 + 8) * N + col) = v1;
            } else {
                int m = col / 768;
                int hc = col - m * 768;
                int h = hc >> 6, d = hc & 63;
                __nv_bfloat16* base = (m == 0 ? Q2o : m == 1 ? K2o : V2o);
                float qs = (m == 0) ? QSC : 1.0f;
                __nv_bfloat162 H, L;
#pragma unroll
                for (int rr = 0; rr < 2; rr++) {
                    int r = r0 + rr * 8;
                    float2 v = rr ? v1 : v0;
                    split2(v.x * qs, v.y * qs, H, L);
                    __nv_bfloat16* dst = base +
                        ((size_t)((r >> 11) * 12 + h) * 2048 + (r & 2047)) * 128 + d;
                    *(__nv_bfloat162*)dst = H;
                    *(__nv_bfloat162*)(dst + 64) = L;
                }
            }
        }
    }
}

// ================= flash attention v10: static-max softmax =================
// P = exp2(S2 - SMAX) — no running max, no alpha rescale, no max shuffles.
// Scale 2^-SMAX cancels via 1/l at merge. |S2| <~ 6 so no overflow possible.
#define AT10_SMEM (34816 + 4 * 17920)

__device__ __forceinline__ void computeS(float (&sc)[4][4], uint32_t Qu, uint32_t Kst,
                                         int wid, int lane) {
#pragma unroll
    for (int nt = 0; nt < 4; nt++)
#pragma unroll
        for (int j = 0; j < 4; j++) sc[nt][j] = 0.f;
#pragma unroll
    for (int g = 0; g < 4; g++) {
        const uint32_t qrow = Qu + (wid * 16 + (lane & 15)) * 272 + g * 32 + (lane >> 4) * 16;
        const uint32_t krow0 = Kst + (lane & 15) * 272 + g * 32 + (lane >> 4) * 16;
        const uint32_t krow1 = Kst + (16 + (lane & 15)) * 272 + g * 32 + (lane >> 4) * 16;
        uint32_t aqh[4], aql[4], bh0[4], bh1[4], bl0[4], bl1[4];
        ldsm4(aqh, qrow);
        ldsm4(aql, qrow + 128);
        ldsm4(bh0, krow0);
        ldsm4(bh1, krow1);
        ldsm4(bl0, krow0 + 128);
        ldsm4(bl1, krow1 + 128);
        mma16816(sc[0], aqh, bh0[0], bh0[2]); mma16816(sc[1], aqh, bh0[1], bh0[3]);
        mma16816(sc[2], aqh, bh1[0], bh1[2]); mma16816(sc[3], aqh, bh1[1], bh1[3]);
        mma16816(sc[0], aql, bh0[0], bh0[2]); mma16816(sc[1], aql, bh0[1], bh0[3]);
        mma16816(sc[2], aql, bh1[0], bh1[2]); mma16816(sc[3], aql, bh1[1], bh1[3]);
        mma16816(sc[0], aqh, bl0[0], bl0[2]); mma16816(sc[1], aqh, bl0[1], bl0[3]);
        mma16816(sc[2], aqh, bl1[0], bl1[2]); mma16816(sc[3], aqh, bl1[1], bl1[3]);
    }
}

__global__ __launch_bounds__(256, 2)
void attn10(const __nv_bfloat16* __restrict__ Q2, const __nv_bfloat16* __restrict__ K2,
            const __nv_bfloat16* __restrict__ V2, float* __restrict__ Op,
            float* __restrict__ Ll) {
    extern __shared__ char sm[];
    const uint32_t sb = smem_u32(sm);
    const uint32_t Qu = sb;

    const int tid = threadIdx.x, wid = tid >> 5, lane = tid & 31;
    const int bh = blockIdx.y;
    const int q0 = blockIdx.x * 128;
    const int half = blockIdx.z;

    const __nv_bfloat16* Qg = Q2 + ((size_t)bh * 2048 + q0) * 128;
    const __nv_bfloat16* Kg0 = K2 + ((size_t)bh * 2048 + half * 1024) * 128;
    const __nv_bfloat16* Vg0 = V2 + ((size_t)bh * 2048 + half * 1024) * 128;

    auto stageK = [&](int st) { return sb + 34816 + st * 17920; };

    auto loadKV = [&](int st, int kt) {
        const __nv_bfloat16* Kg = Kg0 + (size_t)kt * 32 * 128;
        const __nv_bfloat16* Vg = Vg0 + (size_t)kt * 32 * 128;
        uint32_t Ku = stageK(st), Vu = Ku + 8704;
#pragma unroll
        for (int i = 0; i < 2; i++) {
            int idx = tid + i * 256;
            int row = idx >> 4, j = idx & 15;
            cp16(Ku + row * 272 + j * 16, Kg + row * 128 + j * 8);
        }
#pragma unroll
        for (int i = 0; i < 2; i++) {
            int idx = tid + i * 256;
            int row = idx >> 3, j = idx & 7;
            cp16(Vu + row * 144 + j * 16,
                 Vg + (row & 31) * 128 + (row >> 5) * 64 + j * 8);
        }
    };

#pragma unroll
    for (int i = 0; i < 8; i++) {
        int idx = tid + i * 256;
        int row = idx >> 4, j = idx & 15;
        cp16(Qu + row * 272 + j * 16, Qg + row * 128 + j * 8);
    }
    loadKV(0, 0);
    cp_commit();
    loadKV(1, 1);
    cp_commit();
    cp_wait1();
    __syncthreads();

    float oc[8][4] = {};
    float lrow[2] = { 0.f, 0.f };       // per-thread partial; quad-reduce at end
    float sc0[4][4], sc1[4][4];

    computeS(sc0, Qu, stageK(0), wid, lane);

    auto body = [&](float (&scCur)[4][4], float (&scNxt)[4][4], int kt) {
        if (kt + 2 < 32) {
            loadKV((kt + 2) & 3, kt + 2);
            cp_commit();
            cp_wait1();
        } else {
            cp_wait0();
        }
        __syncthreads();   // orders KV(kt+1) visibility AND prior PV reads

        if (kt + 1 < 32)
            computeS(scNxt, Qu, stageK((kt + 1) & 3), wid, lane);

        // ---- static-max softmax: P = exp2(S2 - SMAX) ----
#pragma unroll
        for (int nt = 0; nt < 4; nt++) {
            scCur[nt][0] = exp2f(scCur[nt][0] - SMAX);
            scCur[nt][1] = exp2f(scCur[nt][1] - SMAX);
            scCur[nt][2] = exp2f(scCur[nt][2] - SMAX);
            scCur[nt][3] = exp2f(scCur[nt][3] - SMAX);
            lrow[0] += scCur[nt][0] + scCur[nt][1];
            lrow[1] += scCur[nt][2] + scCur[nt][3];
        }

        const uint32_t Vst = stageK(kt & 3) + 8704;
#pragma unroll
        for (int kg = 0; kg < 2; kg++) {
            uint32_t Ph[4], Pl[4];
#pragma unroll
            for (int e = 0; e < 2; e++) {
                const float* f0 = scCur[kg * 2];
                const float* f1 = scCur[kg * 2 + 1];
                __nv_bfloat162 H, L;
                split2(f0[e * 2], f0[e * 2 + 1], H, L);
                Ph[e] = *(uint32_t*)&H; Pl[e] = *(uint32_t*)&L;
                split2(f1[e * 2], f1[e * 2 + 1], H, L);
                Ph[e + 2] = *(uint32_t*)&H; Pl[e + 2] = *(uint32_t*)&L;
            }
#pragma unroll
            for (int vt = 0; vt < 2; vt++) {
                uint32_t bv[4][4];
#pragma unroll
                for (int p = 0; p < 4; p++)
                    ldsm4t(bv[p], Vst + (vt * 32 + kg * 16 + (lane & 15)) * 144 +
                                   p * 32 + (lane >> 4) * 16);
#pragma unroll
                for (int p = 0; p < 4; p++)
#pragma unroll
                    for (int j = 0; j < 2; j++) {
                        mma16816(oc[p * 2 + j], Ph, bv[p][j * 2], bv[p][j * 2 + 1]);
                        if (vt == 0)
                            mma16816(oc[p * 2 + j], Pl, bv[p][j * 2], bv[p][j * 2 + 1]);
                    }
            }
        }
    };

    for (int kt = 0; kt < 32; kt += 2) {
        body(sc0, sc1, kt);
        body(sc1, sc0, kt + 1);
    }

    lrow[0] += __shfl_xor_sync(0xffffffffu, lrow[0], 1);
    lrow[0] += __shfl_xor_sync(0xffffffffu, lrow[0], 2);
    lrow[1] += __shfl_xor_sync(0xffffffffu, lrow[1], 1);
    lrow[1] += __shfl_xor_sync(0xffffffffu, lrow[1], 2);

    // ---- epilogue: partial fp32 O, l ----
    {
        int r = q0 + wid * 16 + (lane >> 2);
        size_t rbase = ((size_t)(half * 24 + bh) * 2048 + r);
        float* op0 = Op + rbase * 64;
        float* op1 = Op + (rbase + 8) * 64;
#pragma unroll
        for (int nt = 0; nt < 8; nt++) {
            int c = nt * 8 + 2 * (lane & 3);
            *(float2*)(op0 + c) = make_float2(oc[nt][0], oc[nt][1]);
            *(float2*)(op1 + c) = make_float2(oc[nt][2], oc[nt][3]);
        }
        if ((lane & 3) == 0) {
            Ll[rbase] = lrow[0];
            Ll[rbase + 8] = lrow[1];
        }
    }
}

// ===== merge halves (plain sums; shared SMAX scale cancels) -> AOr tf32 fp32 =====
__global__ void mergeO(const float* __restrict__ Op, const float* __restrict__ Ll,
                       float* __restrict__ AOr) {
    int i = blockIdx.x * blockDim.x + threadIdx.x;
    if (i >= 24 * 2048 * 8) return;
    int cg = i & 7;
    int row = (i >> 3) & 2047;
    int bh = i >> 14;
    int b = bh / 12, h = bh % 12;

    size_t r1 = (size_t)bh * 2048 + row;
    size_t r2 = (size_t)(24 + bh) * 2048 + row;
    float inv = 1.0f / (Ll[r1] + Ll[r2]);

    const float* o1 = Op + r1 * 64 + cg * 8;
    const float* o2 = Op + r2 * 64 + cg * 8;
    float4 p1a = *(const float4*)o1, p1b = *(const float4*)(o1 + 4);
    float4 p2a = *(const float4*)o2, p2b = *(const float4*)(o2 + 4);

    float4 va, vb;
    va.x = tf32r((p1a.x + p2a.x) * inv); va.y = tf32r((p1a.y + p2a.y) * inv);
    va.z = tf32r((p1a.z + p2a.z) * inv); va.w = tf32r((p1a.w + p2a.w) * inv);
    vb.x = tf32r((p1b.x + p2b.x) * inv); vb.y = tf32r((p1b.y + p2b.y) * inv);
    vb.z = tf32r((p1b.z + p2b.z) * inv); vb.w = tf32r((p1b.w + p2b.w) * inv);

    float* base = AOr + (size_t)(b * 2048 + row) * 768 + h * 64 + cg * 8;
    *(float4*)base = va;
    *(float4*)(base + 4) = vb;
}

// ---------------- launch ----------------
extern "C" void kernel_launch(void* const* d_in, const int* in_sizes, int n_in,
                              void* d_out, int out_size) {
    const float* x      = (const float*)d_in[0];
    const float* qkv_w  = (const float*)d_in[1];
    const float* qkv_b  = (const float*)d_in[2];
    const float* proj_w = (const float*)d_in[3];
    const float* proj_b = (const float*)d_in[4];
    float* out = (float*)d_out;

    float *Xr, *W1r, *W2r, *AOr, *Op, *Ll;
    __nv_bfloat16 *Q2, *K2, *V2;
    cudaGetSymbolAddress((void**)&Xr,  g_Xr);
    cudaGetSymbolAddress((void**)&W1r, g_W1r);
    cudaGetSymbolAddress((void**)&W2r, g_W2r);
    cudaGetSymbolAddress((void**)&AOr, g_AOr);
    cudaGetSymbolAddress((void**)&Q2,  g_Q2);
    cudaGetSymbolAddress((void**)&K2,  g_K2);
    cudaGetSymbolAddress((void**)&V2,  g_V2);
    cudaGetSymbolAddress((void**)&Op,  g_Op);
    cudaGetSymbolAddress((void**)&Ll,  g_Ll);

    const int gemm_smem_128 = 3 * (128 + 128) * 128;   // 98304
    const int gemm_smem_64  = 3 * (128 + 64) * 128;    // 73728
    cudaFuncSetAttribute(tf32_gemm<128>, cudaFuncAttributeMaxDynamicSharedMemorySize, gemm_smem_128);
    cudaFuncSetAttribute(tf32_gemm<64>,  cudaFuncAttributeMaxDynamicSharedMemorySize, gemm_smem_64);
    cudaFuncSetAttribute(attn10, cudaFuncAttributeMaxDynamicSharedMemorySize, AT10_SMEM);

    rnd32<<<(4096 * 192 + 255) / 256, 256>>>(x, Xr, 4096 * 192);
    rnd32<<<(2304 * 192 + 255) / 256, 256>>>(qkv_w, W1r, 2304 * 192);
    rnd32<<<(768 * 192 + 255) / 256, 256>>>(proj_w, W2r, 768 * 192);

    // 1) qkv = x @ qkv_w^T + qkv_b (tf32), fused per-head hi/lo split out
    tf32_gemm<128><<<dim3(18, 32), 256, gemm_smem_128>>>(Xr, W1r, qkv_b, nullptr,
                                                         Q2, K2, V2, 1, 4096, 2304, 768);

    // 2) attention: kv halves -> partial (O,l), merge -> AOr
    attn10<<<dim3(16, 24, 2), 256, AT10_SMEM>>>(Q2, K2, V2, Op, Ll);
    mergeO<<<(24 * 2048 * 8 + 255) / 256, 256>>>(Op, Ll, AOr);

    // 3) out = ao @ proj_w^T + proj_b (tf32)
    tf32_gemm<64><<<dim3(12, 32), 256, gemm_smem_64>>>(AOr, W2r, proj_b, out,
                                                       nullptr, nullptr, nullptr, 0, 4096, 768, 768);
}

// round 17
// speedup vs baseline: 1.4949x; 1.0245x over previous
#include <cuda_runtime.h>
#include <cuda_bf16.h>
#include <cstdint>

// ---------------- scratch (no cudaMalloc allowed) ----------------
__device__ float g_Xr [4096 * 768];                  // x, tf32-rounded
__device__ float g_W1r[2304 * 768];                  // qkv_w, tf32-rounded
__device__ float g_W2r[768 * 768];                   // proj_w, tf32-rounded
__device__ float g_AOr[4096 * 768];                  // attention out, tf32-rounded
__device__ __nv_bfloat16 g_Q2[24 * 2048 * 128];      // per-head hi|lo (Q pre-scaled)
__device__ __nv_bfloat16 g_K2[24 * 2048 * 128];
__device__ __nv_bfloat16 g_V2[24 * 2048 * 128];
__device__ float g_Op[2 * 24 * 2048 * 64];           // partial O  [half][bh][row][d]
__device__ float g_Ll[2 * 24 * 2048];                // partial l   [half][bh][row]

#define QSC 0.18033688f   // 0.125 * log2(e)
#define SMAX 16.0f        // static softmax exponent offset

// ================= helpers =================
__device__ __forceinline__ uint32_t smem_u32(const void* p) {
    uint32_t a;
    asm("{ .reg .u64 t; cvta.to.shared.u64 t, %1; cvt.u32.u64 %0, t; }" : "=r"(a) : "l"(p));
    return a;
}
__device__ __forceinline__ void ldsm4(uint32_t* r, uint32_t a) {
    asm volatile("ldmatrix.sync.aligned.m8n8.x4.shared.b16 {%0,%1,%2,%3}, [%4];"
                 : "=r"(r[0]), "=r"(r[1]), "=r"(r[2]), "=r"(r[3]) : "r"(a));
}
__device__ __forceinline__ void ldsm4t(uint32_t* r, uint32_t a) {
    asm volatile("ldmatrix.sync.aligned.m8n8.x4.trans.shared.b16 {%0,%1,%2,%3}, [%4];"
                 : "=r"(r[0]), "=r"(r[1]), "=r"(r[2]), "=r"(r[3]) : "r"(a));
}
__device__ __forceinline__ void mma16816(float* d, const uint32_t* a, uint32_t b0, uint32_t b1) {
    asm volatile("mma.sync.aligned.m16n8k16.row.col.f32.bf16.bf16.f32 "
                 "{%0,%1,%2,%3},{%4,%5,%6,%7},{%8,%9},{%0,%1,%2,%3};"
                 : "+f"(d[0]), "+f"(d[1]), "+f"(d[2]), "+f"(d[3])
                 : "r"(a[0]), "r"(a[1]), "r"(a[2]), "r"(a[3]), "r"(b0), "r"(b1));
}
__device__ __forceinline__ void mma_tf32(float* d, const uint32_t* a, uint32_t b0, uint32_t b1) {
    asm volatile("mma.sync.aligned.m16n8k8.row.col.f32.tf32.tf32.f32 "
                 "{%0,%1,%2,%3},{%4,%5,%6,%7},{%8,%9},{%0,%1,%2,%3};"
                 : "+f"(d[0]), "+f"(d[1]), "+f"(d[2]), "+f"(d[3])
                 : "r"(a[0]), "r"(a[1]), "r"(a[2]), "r"(a[3]), "r"(b0), "r"(b1));
}
__device__ __forceinline__ void cp16(uint32_t saddr, const void* gaddr) {
    asm volatile("cp.async.cg.shared.global [%0], [%1], 16;" :: "r"(saddr), "l"(gaddr));
}
__device__ __forceinline__ void cp_commit() { asm volatile("cp.async.commit_group;" ::: "memory"); }
__device__ __forceinline__ void cp_wait1()  { asm volatile("cp.async.wait_group 1;" ::: "memory"); }
__device__ __forceinline__ void cp_wait0()  { asm volatile("cp.async.wait_group 0;" ::: "memory"); }

__device__ __forceinline__ float tf32r(float x) {
    uint32_t r;
    asm("cvt.rna.tf32.f32 %0, %1;" : "=r"(r) : "f"(x));
    return __uint_as_float(r);
}
__device__ __forceinline__ void split2(float x, float y, __nv_bfloat162& hi, __nv_bfloat162& lo) {
    hi = __float22bfloat162_rn(make_float2(x, y));
    float2 b = __bfloat1622float2(hi);
    lo = __float22bfloat162_rn(make_float2(x - b.x, y - b.y));
}

// ===== fused tf32 rounding of all three inputs (one launch) =====
// float4 counts: x 4096*768/4 = 786432 ; qkv_w 2304*768/4 = 442368 ; proj_w 768*768/4 = 147456
#define N4_X  786432
#define N4_W1 442368
#define N4_W2 147456
__global__ void rnd32all(const float* __restrict__ x, const float* __restrict__ w1,
                         const float* __restrict__ w2, float* __restrict__ Xr,
                         float* __restrict__ W1r, float* __restrict__ W2r) {
    int i = blockIdx.x * blockDim.x + threadIdx.x;
    const float* src;
    float* dst;
    int k;
    if (i < N4_X)                    { src = x;  dst = Xr;  k = i; }
    else if (i < N4_X + N4_W1)       { src = w1; dst = W1r; k = i - N4_X; }
    else if (i < N4_X + N4_W1 + N4_W2) { src = w2; dst = W2r; k = i - N4_X - N4_W1; }
    else return;
    float4 v = ((const float4*)src)[k];
    v.x = tf32r(v.x); v.y = tf32r(v.y); v.z = tf32r(v.z); v.w = tf32r(v.w);
    ((float4*)dst)[k] = v;
}

// ================= TF32 GEMM (validated R14) =================
template<int BN>
__global__ __launch_bounds__(256, 2)
void tf32_gemm(const float* __restrict__ A, const float* __restrict__ B,
               const float* __restrict__ bias, float* __restrict__ C,
               __nv_bfloat16* __restrict__ Q2o, __nv_bfloat16* __restrict__ K2o,
               __nv_bfloat16* __restrict__ V2o, int splitOut,
               int M, int N, int K) {
    constexpr int WN = BN / 2;
    constexpr int NT = WN / 8;
    constexpr int ASTG = 128 * 128;
    constexpr int BSTG = BN * 128;
    constexpr int STAGE = ASTG + BSTG;

    extern __shared__ char sm[];
    const uint32_t sb = smem_u32(sm);
    const int tid = threadIdx.x, wid = tid >> 5, lane = tid & 31;
    const int wm = wid & 3, wn = wid >> 2;
    const int mBase = blockIdx.y * 128, nBase = blockIdx.x * BN;
    const int NIT = K / 32;

    float acc[2][NT][4] = {};

    auto load_stage = [&](int st, int k0) {
        uint32_t sA = sb + st * STAGE, sB2 = sA + ASTG;
#pragma unroll
        for (int i2 = 0; i2 < 4; i2++) {
            int c = tid + i2 * 256;
            int row = c >> 3, j = c & 7;
            cp16(sA + row * 128 + ((j ^ (row & 7)) << 4),
                 A + (size_t)(mBase + row) * K + k0 + j * 4);
        }
#pragma unroll
        for (int i2 = 0; i2 < BN / 32; i2++) {
            int c = tid + i2 * 256;
            int row = c >> 3, j = c & 7;
            cp16(sB2 + row * 128 + ((j ^ (row & 7)) << 4),
                 B + (size_t)(nBase + row) * K + k0 + j * 4);
        }
    };

    load_stage(0, 0);  cp_commit();
    load_stage(1, 32); cp_commit();

    for (int it = 0; it < NIT; it++) {
        if (it + 2 < NIT) cp_wait1(); else cp_wait0();
        __syncthreads();
        if (it + 2 < NIT) { load_stage((it + 2) % 3, (it + 2) * 32); cp_commit(); }

        uint32_t sA = sb + (it % 3) * STAGE, sB2 = sA + ASTG;
#pragma unroll
        for (int s = 0; s < 4; s++) {
            uint32_t a[2][4], bq[NT / 2][4];
            int tA = lane >> 3;
#pragma unroll
            for (int mt = 0; mt < 2; mt++) {
                int row = wm * 32 + mt * 16 + (tA & 1) * 8 + (lane & 7);
                int chunk = s * 2 + (tA >> 1);
                ldsm4(a[mt], sA + row * 128 + ((chunk ^ (row & 7)) << 4));
            }
#pragma unroll
            for (int p2 = 0; p2 < NT / 2; p2++) {
                int nrow = wn * WN + p2 * 16 + (tA >> 1) * 8 + (lane & 7);
                int chunk = s * 2 + (tA & 1);
                ldsm4(bq[p2], sB2 + nrow * 128 + ((chunk ^ (nrow & 7)) << 4));
            }
#pragma unroll
            for (int mt = 0; mt < 2; mt++)
#pragma unroll
                for (int nt = 0; nt < NT; nt++) {
                    int p2 = nt >> 1, j = nt & 1;
                    mma_tf32(acc[mt][nt], a[mt], bq[p2][j * 2], bq[p2][j * 2 + 1]);
                }
        }
    }

    const int cbase = nBase + wn * WN;
#pragma unroll
    for (int nt = 0; nt < NT; nt++) {
        int col = cbase + nt * 8 + 2 * (lane & 3);
        float2 bv = *(const float2*)(bias + col);
#pragma unroll
        for (int mt = 0; mt < 2; mt++) {
            int r0 = mBase + wm * 32 + mt * 16 + (lane >> 2);
            float2 v0; v0.x = acc[mt][nt][0] + bv.x; v0.y = acc[mt][nt][1] + bv.y;
            float2 v1; v1.x = acc[mt][nt][2] + bv.x; v1.y = acc[mt][nt][3] + bv.y;
            if (!splitOut) {
                *(float2*)(C + (size_t)r0 * N + col) = v0;
                *(float2*)(C + (size_t)(r0 + 8) * N + col) = v1;
            } else {
                int m = col / 768;
                int hc = col - m * 768;
                int h = hc >> 6, d = hc & 63;
                __nv_bfloat16* base = (m == 0 ? Q2o : m == 1 ? K2o : V2o);
                float qs = (m == 0) ? QSC : 1.0f;
                __nv_bfloat162 H, L;
#pragma unroll
                for (int rr = 0; rr < 2; rr++) {
                    int r = r0 + rr * 8;
                    float2 v = rr ? v1 : v0;
                    split2(v.x * qs, v.y * qs, H, L);
                    __nv_bfloat16* dst = base +
                        ((size_t)((r >> 11) * 12 + h) * 2048 + (r & 2047)) * 128 + d;
                    *(__nv_bfloat162*)dst = H;
                    *(__nv_bfloat162*)(dst + 64) = L;
                }
            }
        }
    }
}

// ================= flash attention v11: literal-stage unroll + interleaved PV ==========
#define AT11_SMEM (34816 + 4 * 17920)

__global__ __launch_bounds__(256, 2)
void attn11(const __nv_bfloat16* __restrict__ Q2, const __nv_bfloat16* __restrict__ K2,
            const __nv_bfloat16* __restrict__ V2, float* __restrict__ Op,
            float* __restrict__ Ll) {
    extern __shared__ char sm[];
    const uint32_t sb = smem_u32(sm);
    const uint32_t Qu = sb;

    const int tid = threadIdx.x, wid = tid >> 5, lane = tid & 31;
    const int bh = blockIdx.y;
    const int q0 = blockIdx.x * 128;
    const int half = blockIdx.z;

    const __nv_bfloat16* Qg = Q2 + ((size_t)bh * 2048 + q0) * 128;
    const __nv_bfloat16* Kg0 = K2 + ((size_t)bh * 2048 + half * 1024) * 128;
    const __nv_bfloat16* Vg0 = V2 + ((size_t)bh * 2048 + half * 1024) * 128;

    const uint32_t qAddr = Qu + (wid * 16 + (lane & 15)) * 272 + (lane >> 4) * 16;
    const uint32_t kOff0 = (lane & 15) * 272 + (lane >> 4) * 16;
    const uint32_t kOff1 = (16 + (lane & 15)) * 272 + (lane >> 4) * 16;
    const uint32_t vOff  = (lane & 15) * 144 + (lane >> 4) * 16;

    auto loadKV = [&](uint32_t KuBase, int kt) __attribute__((always_inline)) {
        const __nv_bfloat16* Kg = Kg0 + (size_t)kt * 32 * 128;
        const __nv_bfloat16* Vg = Vg0 + (size_t)kt * 32 * 128;
        uint32_t Vu = KuBase + 8704;
#pragma unroll
        for (int i = 0; i < 2; i++) {
            int idx = tid + i * 256;
            int row = idx >> 4, j = idx & 15;
            cp16(KuBase + row * 272 + j * 16, Kg + row * 128 + j * 8);
        }
#pragma unroll
        for (int i = 0; i < 2; i++) {
            int idx = tid + i * 256;
            int row = idx >> 3, j = idx & 7;
            cp16(Vu + row * 144 + j * 16,
                 Vg + (row & 31) * 128 + (row >> 5) * 64 + j * 8);
        }
    };

    auto computeS = [&](float (&sc)[4][4], uint32_t Kst) __attribute__((always_inline)) {
#pragma unroll
        for (int nt = 0; nt < 4; nt++)
#pragma unroll
            for (int j = 0; j < 4; j++) sc[nt][j] = 0.f;
#pragma unroll
        for (int g = 0; g < 4; g++) {
            uint32_t aqh[4], aql[4], bh0[4], bh1[4], bl0[4], bl1[4];
            ldsm4(aqh, qAddr + g * 32);
            ldsm4(aql, qAddr + g * 32 + 128);
            ldsm4(bh0, Kst + kOff0 + g * 32);
            ldsm4(bh1, Kst + kOff1 + g * 32);
            ldsm4(bl0, Kst + kOff0 + g * 32 + 128);
            ldsm4(bl1, Kst + kOff1 + g * 32 + 128);
            mma16816(sc[0], aqh, bh0[0], bh0[2]); mma16816(sc[1], aqh, bh0[1], bh0[3]);
            mma16816(sc[2], aqh, bh1[0], bh1[2]); mma16816(sc[3], aqh, bh1[1], bh1[3]);
            mma16816(sc[0], aql, bh0[0], bh0[2]); mma16816(sc[1], aql, bh0[1], bh0[3]);
            mma16816(sc[2], aql, bh1[0], bh1[2]); mma16816(sc[3], aql, bh1[1], bh1[3]);
            mma16816(sc[0], aqh, bl0[0], bl0[2]); mma16816(sc[1], aqh, bl0[1], bl0[3]);
            mma16816(sc[2], aqh, bl1[0], bl1[2]); mma16816(sc[3], aqh, bl1[1], bl1[3]);
        }
    };

#pragma unroll
    for (int i = 0; i < 8; i++) {
        int idx = tid + i * 256;
        int row = idx >> 4, j = idx & 15;
        cp16(Qu + row * 272 + j * 16, Qg + row * 128 + j * 8);
    }
    loadKV(sb + 34816, 0);
    cp_commit();
    loadKV(sb + 34816 + 17920, 1);
    cp_commit();
    cp_wait1();
    __syncthreads();

    float oc[8][4] = {};
    float lrow[2] = { 0.f, 0.f };
    float sc0[4][4], sc1[4][4];

    computeS(sc0, sb + 34816);

    auto body = [&](float (&scCur)[4][4], float (&scNxt)[4][4], int kt,
                    uint32_t stC, uint32_t stN, uint32_t stL) __attribute__((always_inline)) {
        if (kt + 2 < 32) {
            loadKV(stL, kt + 2);
            cp_commit();
            cp_wait1();
        } else {
            cp_wait0();
        }
        __syncthreads();

        if (kt + 1 < 32)
            computeS(scNxt, stN);

        const uint32_t Vst = stC + 8704;

#pragma unroll
        for (int kg = 0; kg < 2; kg++) {
            float* e0 = scCur[kg * 2];
            float* e1 = scCur[kg * 2 + 1];
            e0[0] = exp2f(e0[0] - SMAX); e0[1] = exp2f(e0[1] - SMAX);
            e0[2] = exp2f(e0[2] - SMAX); e0[3] = exp2f(e0[3] - SMAX);
            e1[0] = exp2f(e1[0] - SMAX); e1[1] = exp2f(e1[1] - SMAX);
            e1[2] = exp2f(e1[2] - SMAX); e1[3] = exp2f(e1[3] - SMAX);
            lrow[0] += e0[0] + e0[1] + e1[0] + e1[1];
            lrow[1] += e0[2] + e0[3] + e1[2] + e1[3];

            uint32_t Ph[4], Pl[4];
            __nv_bfloat162 H, L;
            split2(e0[0], e0[1], H, L); Ph[0] = *(uint32_t*)&H; Pl[0] = *(uint32_t*)&L;
            split2(e0[2], e0[3], H, L); Ph[1] = *(uint32_t*)&H; Pl[1] = *(uint32_t*)&L;
            split2(e1[0], e1[1], H, L); Ph[2] = *(uint32_t*)&H; Pl[2] = *(uint32_t*)&L;
            split2(e1[2], e1[3], H, L); Ph[3] = *(uint32_t*)&H; Pl[3] = *(uint32_t*)&L;

#pragma unroll
            for (int vt = 0; vt < 2; vt++) {
                uint32_t bv[4][4];
#pragma unroll
                for (int p = 0; p < 4; p++)
                    ldsm4t(bv[p], Vst + vOff + (vt * 32 + kg * 16) * 144 + p * 32);
#pragma unroll
                for (int p = 0; p < 4; p++)
#pragma unroll
                    for (int j = 0; j < 2; j++) {
                        mma16816(oc[p * 2 + j], Ph, bv[p][j * 2], bv[p][j * 2 + 1]);
                        if (vt == 0)
                            mma16816(oc[p * 2 + j], Pl, bv[p][j * 2], bv[p][j * 2 + 1]);
                    }
            }
        }
    };

    const uint32_t S0 = sb + 34816, S1 = S0 + 17920, S2s = S0 + 35840, S3 = S0 + 53760;
    for (int kt = 0; kt < 32; kt += 4) {
        body(sc0, sc1, kt,     S0, S1, S2s);
        body(sc1, sc0, kt + 1, S1, S2s, S3);
        body(sc0, sc1, kt + 2, S2s, S3, S0);
        body(sc1, sc0, kt + 3, S3, S0, S1);
    }

    lrow[0] += __shfl_xor_sync(0xffffffffu, lrow[0], 1);
    lrow[0] += __shfl_xor_sync(0xffffffffu, lrow[0], 2);
    lrow[1] += __shfl_xor_sync(0xffffffffu, lrow[1], 1);
    lrow[1] += __shfl_xor_sync(0xffffffffu, lrow[1], 2);

    {
        int r = q0 + wid * 16 + (lane >> 2);
        size_t rbase = ((size_t)(half * 24 + bh) * 2048 + r);
        float* op0 = Op + rbase * 64;
        float* op1 = Op + (rbase + 8) * 64;
#pragma unroll
        for (int nt = 0; nt < 8; nt++) {
            int c = nt * 8 + 2 * (lane & 3);
            *(float2*)(op0 + c) = make_float2(oc[nt][0], oc[nt][1]);
            *(float2*)(op1 + c) = make_float2(oc[nt][2], oc[nt][3]);
        }
        if ((lane & 3) == 0) {
            Ll[rbase] = lrow[0];
            Ll[rbase + 8] = lrow[1];
        }
    }
}

// ===== merge halves -> AOr tf32 fp32 =====
__global__ void mergeO(const float* __restrict__ Op, const float* __restrict__ Ll,
                       float* __restrict__ AOr) {
    int i = blockIdx.x * blockDim.x + threadIdx.x;
    if (i >= 24 * 2048 * 8) return;
    int cg = i & 7;
    int row = (i >> 3) & 2047;
    int bh = i >> 14;
    int b = bh / 12, h = bh % 12;

    size_t r1 = (size_t)bh * 2048 + row;
    size_t r2 = (size_t)(24 + bh) * 2048 + row;
    float inv = 1.0f / (Ll[r1] + Ll[r2]);

    const float* o1 = Op + r1 * 64 + cg * 8;
    const float* o2 = Op + r2 * 64 + cg * 8;
    float4 p1a = *(const float4*)o1, p1b = *(const float4*)(o1 + 4);
    float4 p2a = *(const float4*)o2, p2b = *(const float4*)(o2 + 4);

    float4 va, vb;
    va.x = tf32r((p1a.x + p2a.x) * inv); va.y = tf32r((p1a.y + p2a.y) * inv);
    va.z = tf32r((p1a.z + p2a.z) * inv); va.w = tf32r((p1a.w + p2a.w) * inv);
    vb.x = tf32r((p1b.x + p2b.x) * inv); vb.y = tf32r((p1b.y + p2b.y) * inv);
    vb.z = tf32r((p1b.z + p2b.z) * inv); vb.w = tf32r((p1b.w + p2b.w) * inv);

    float* base = AOr + (size_t)(b * 2048 + row) * 768 + h * 64 + cg * 8;
    *(float4*)base = va;
    *(float4*)(base + 4) = vb;
}

// ---------------- launch ----------------
extern "C" void kernel_launch(void* const* d_in, const int* in_sizes, int n_in,
                              void* d_out, int out_size) {
    const float* x      = (const float*)d_in[0];
    const float* qkv_w  = (const float*)d_in[1];
    const float* qkv_b  = (const float*)d_in[2];
    const float* proj_w = (const float*)d_in[3];
    const float* proj_b = (const float*)d_in[4];
    float* out = (float*)d_out;

    float *Xr, *W1r, *W2r, *AOr, *Op, *Ll;
    __nv_bfloat16 *Q2, *K2, *V2;
    cudaGetSymbolAddress((void**)&Xr,  g_Xr);
    cudaGetSymbolAddress((void**)&W1r, g_W1r);
    cudaGetSymbolAddress((void**)&W2r, g_W2r);
    cudaGetSymbolAddress((void**)&AOr, g_AOr);
    cudaGetSymbolAddress((void**)&Q2,  g_Q2);
    cudaGetSymbolAddress((void**)&K2,  g_K2);
    cudaGetSymbolAddress((void**)&V2,  g_V2);
    cudaGetSymbolAddress((void**)&Op,  g_Op);
    cudaGetSymbolAddress((void**)&Ll,  g_Ll);

    const int gemm_smem_128 = 3 * (128 + 128) * 128;   // 98304
    const int gemm_smem_64  = 3 * (128 + 64) * 128;    // 73728
    cudaFuncSetAttribute(tf32_gemm<128>, cudaFuncAttributeMaxDynamicSharedMemorySize, gemm_smem_128);
    cudaFuncSetAttribute(tf32_gemm<64>,  cudaFuncAttributeMaxDynamicSharedMemorySize, gemm_smem_64);
    cudaFuncSetAttribute(attn11, cudaFuncAttributeMaxDynamicSharedMemorySize, AT11_SMEM);

    // fused tf32 rounding of all inputs (fixed float4 counts)
    const int totalN4 = N4_X + N4_W1 + N4_W2;   // 1376256
    rnd32all<<<(totalN4 + 255) / 256, 256>>>(x, qkv_w, proj_w, Xr, W1r, W2r);

    // 1) qkv = x @ qkv_w^T + qkv_b (tf32), fused per-head hi/lo split out
    tf32_gemm<128><<<dim3(18, 32), 256, gemm_smem_128>>>(Xr, W1r, qkv_b, nullptr,
                                                         Q2, K2, V2, 1, 4096, 2304, 768);

    // 2) attention: kv halves -> partial (O,l), merge -> AOr
    attn11<<<dim3(16, 24, 2), 256, AT11_SMEM>>>(Q2, K2, V2, Op, Ll);
    mergeO<<<(24 * 2048 * 8 + 255) / 256, 256>>>(Op, Ll, AOr);

    // 3) out = ao @ proj_w^T + proj_b (tf32)
    tf32_gemm<64><<<dim3(12, 32), 256, gemm_smem_64>>>(AOr, W2r, proj_b, out,
                                                       nullptr, nullptr, nullptr, 0, 4096, 768, 768);
}